// round 10
// baseline (speedup 1.0000x reference)
#include <cuda_runtime.h>

typedef unsigned int u32;

#define SEQ 2048
#define HIDDEN 2048
#define NH 16
#define NKV 2
#define HD 128
#define KVW (NKV*HD)          // 256
#define ATT_SCALE 0.08838834764831845f

// ---------------- scratch (no allocations allowed) ----------------
__device__ float g_Q[SEQ*HIDDEN];
__device__ float g_K[SEQ*KVW];
__device__ float g_V[SEQ*KVW];
__device__ float g_C[SEQ*HIDDEN];

// ---------------- helpers ----------------
__device__ __forceinline__ u32 f2tf32(float f) {
    u32 r;
    asm("cvt.rna.tf32.f32 %0, %1;" : "=r"(r) : "f"(f));
    return r;
}
__device__ __forceinline__ void mma_tf32(float* c, const u32* a, const u32* b) {
    asm volatile(
        "mma.sync.aligned.m16n8k8.row.col.f32.tf32.tf32.f32 "
        "{%0,%1,%2,%3}, {%4,%5,%6,%7}, {%8,%9}, {%0,%1,%2,%3};"
        : "+f"(c[0]), "+f"(c[1]), "+f"(c[2]), "+f"(c[3])
        : "r"(a[0]), "r"(a[1]), "r"(a[2]), "r"(a[3]),
          "r"(b[0]), "r"(b[1]));
}
__device__ __forceinline__ void mma_f16(float* c, const u32* a, const u32* b) {
    asm volatile(
        "mma.sync.aligned.m16n8k16.row.col.f32.f16.f16.f32 "
        "{%0,%1,%2,%3}, {%4,%5,%6,%7}, {%8,%9}, {%0,%1,%2,%3};"
        : "+f"(c[0]), "+f"(c[1]), "+f"(c[2]), "+f"(c[3])
        : "r"(a[0]), "r"(a[1]), "r"(a[2]), "r"(a[3]),
          "r"(b[0]), "r"(b[1]));
}
// pack two fp32 -> f16x2; 'lo' occupies the low half. Used identically for
// P (even key in lo) and V (even key in lo) so the pairing is consistent
// regardless of cvt operand-order convention.
__device__ __forceinline__ u32 pack_h2(float lo, float hi) {
    u32 r;
    asm("cvt.rn.f16x2.f32 %0, %1, %2;" : "=r"(r) : "f"(hi), "f"(lo));
    return r;
}

// ---------------------------------------------------------------------------
// tf32 mma.sync GEMM (round-8 verbatim): 128x128 tile, 8 warps (2Mx4N),
// K-chunk 32, double-buffered smem, ONE barrier per chunk, reg staging.
// mode 1: fused QKV (blocks 0-15 -> Q, 16-17 -> K, 18-19 -> V), mode 0: O-proj.
// ---------------------------------------------------------------------------
#define G_SA_LD 36
#define G_SB_LD 132
#define G_STAGE_A (128*G_SA_LD)              // 4608 words
#define G_STAGE (G_STAGE_A + 32*G_SB_LD)     // 8832 words
#define G_SMEM (2*G_STAGE*4)                 // 70656 B

__device__ __forceinline__ void gemm_stage_store(
    u32* buf, const float4* ar, const float4* br,
    int arow, int ak4, int bkrow, int bcol4)
{
    #pragma unroll
    for (int p = 0; p < 4; p++) {
        u32* da = buf + (arow + p * 32) * G_SA_LD + ak4;
        da[0] = f2tf32(ar[p].x); da[1] = f2tf32(ar[p].y);
        da[2] = f2tf32(ar[p].z); da[3] = f2tf32(ar[p].w);
        u32* db = buf + G_STAGE_A + (bkrow + p * 8) * G_SB_LD + bcol4;
        db[0] = f2tf32(br[p].x); db[1] = f2tf32(br[p].y);
        db[2] = f2tf32(br[p].z); db[3] = f2tf32(br[p].w);
    }
}

__global__ void __launch_bounds__(256) mma_gemm_kernel(
    const float* __restrict__ A_ext,
    const float* __restrict__ W0, const float* __restrict__ W1,
    const float* __restrict__ W2,
    const float* __restrict__ b0, const float* __restrict__ b1,
    const float* __restrict__ b2,
    float* __restrict__ outF, int mode)
{
    extern __shared__ u32 smg[];
    const int t = threadIdx.x;
    const int wid = t >> 5, lane = t & 31;
    const int warpM = wid & 1, warpN = wid >> 1;
    const int g = lane >> 2, tg = lane & 3;
    const int row0 = blockIdx.y * 128;

    const float* A; const float* W; const float* bias; float* C; int Nw; int col0;
    if (mode == 1) {
        A = A_ext;
        const int bn = blockIdx.x;
        if (bn < 16)      { W = W0; bias = b0; C = g_Q; Nw = HIDDEN; col0 = bn * 128; }
        else if (bn < 18) { W = W1; bias = b1; C = g_K; Nw = KVW;    col0 = (bn - 16) * 128; }
        else              { W = W2; bias = b2; C = g_V; Nw = KVW;    col0 = (bn - 18) * 128; }
    } else {
        A = g_C; W = W0; bias = nullptr; C = outF; Nw = HIDDEN; col0 = blockIdx.x * 128;
    }

    float c[4][4][4];
    #pragma unroll
    for (int i = 0; i < 4; i++)
        #pragma unroll
        for (int j = 0; j < 4; j++)
            #pragma unroll
            for (int r = 0; r < 4; r++) c[i][j][r] = 0.f;

    const int arow = t >> 3;
    const int ak4  = (t & 7) * 4;
    const int bkrow = t >> 5;
    const int bcol4 = (t & 31) * 4;

    const float* Ap = A + (size_t)(row0 + arow) * HIDDEN + ak4;
    const float* Bp = W + (size_t)bkrow * Nw + col0 + bcol4;
    const size_t aRow32 = (size_t)32 * HIDDEN;
    const size_t bRow8  = (size_t)8 * Nw;
    const int NCH = HIDDEN >> 5;

    float4 ar[4], br[4];
    #pragma unroll
    for (int p = 0; p < 4; p++) {
        ar[p] = *(const float4*)(Ap + p * aRow32);
        br[p] = *(const float4*)(Bp + p * bRow8);
    }
    gemm_stage_store(smg, ar, br, arow, ak4, bkrow, bcol4);
    #pragma unroll
    for (int p = 0; p < 4; p++) {
        ar[p] = *(const float4*)(Ap + 32 + p * aRow32);
        br[p] = *(const float4*)(Bp + (size_t)32 * Nw + p * bRow8);
    }

    const int bcolw = warpN * 32;

    for (int ch = 0; ch < NCH; ch++) {
        __syncthreads();

        if (ch + 1 < NCH)
            gemm_stage_store(smg + ((ch + 1) & 1) * G_STAGE, ar, br,
                             arow, ak4, bkrow, bcol4);

        if (ch + 2 < NCH) {
            const int ko = (ch + 2) * 32;
            #pragma unroll
            for (int p = 0; p < 4; p++) {
                ar[p] = *(const float4*)(Ap + ko + p * aRow32);
                br[p] = *(const float4*)(Bp + (size_t)ko * Nw + p * bRow8);
            }
        }

        const u32* sA = smg + (ch & 1) * G_STAGE;
        const u32* sB = sA + G_STAGE_A;
        const u32* sAw = sA + (warpM * 64) * G_SA_LD;

        #pragma unroll
        for (int ks = 0; ks < 4; ks++) {
            const int kb = ks * 8;
            u32 af[4][4], bf[4][2];
            #pragma unroll
            for (int i = 0; i < 4; i++) {
                const u32* base = sAw + (i * 16 + g) * G_SA_LD + kb + tg;
                af[i][0] = base[0];
                af[i][1] = base[8 * G_SA_LD];
                af[i][2] = base[4];
                af[i][3] = base[8 * G_SA_LD + 4];
            }
            #pragma unroll
            for (int j = 0; j < 4; j++) {
                const u32* base = sB + (kb + tg) * G_SB_LD + bcolw + j * 8 + g;
                bf[j][0] = base[0];
                bf[j][1] = base[4 * G_SB_LD];
            }
            #pragma unroll
            for (int i = 0; i < 4; i++)
                #pragma unroll
                for (int j = 0; j < 4; j++)
                    mma_tf32(c[i][j], af[i], bf[j]);
        }
    }

    #pragma unroll
    for (int i = 0; i < 4; i++) {
        const int r0e = row0 + warpM * 64 + i * 16 + g;
        #pragma unroll
        for (int j = 0; j < 4; j++) {
            const int col = col0 + warpN * 32 + j * 8 + 2 * tg;
            float bb0 = 0.f, bb1 = 0.f;
            if (bias) { bb0 = bias[col]; bb1 = bias[col + 1]; }
            *(float2*)(C + (size_t)r0e * Nw + col) =
                make_float2(c[i][j][0] + bb0, c[i][j][1] + bb1);
            *(float2*)(C + (size_t)(r0e + 8) * Nw + col) =
                make_float2(c[i][j][2] + bb0, c[i][j][3] + bb1);
        }
    }
}

// ---------------------------------------------------------------------------
// RoPE in place (round-4 verbatim)
// ---------------------------------------------------------------------------
__global__ void rope_kernel(const float* __restrict__ cosT,
                            const float* __restrict__ sinT,
                            int nheads, int which)
{
    float* X = which ? g_Q : g_K;
    const int idx = blockIdx.x * blockDim.x + threadIdx.x;
    const int total = SEQ * nheads * 64;
    if (idx >= total) return;
    const int d = idx & 63;
    const int h = (idx >> 6) % nheads;
    const int s = idx / (64 * nheads);

    const float c1 = cosT[s * HD + d];
    const float s1 = sinT[s * HD + d];
    const float c2 = cosT[s * HD + d + 64];
    const float s2 = sinT[s * HD + d + 64];

    float* p = X + (size_t)s * (nheads * HD) + h * HD + d;
    const float x1 = p[0];
    const float x2 = p[64];
    p[0]  = x1 * c1 - x2 * s1;
    p[64] = x2 * c2 + x1 * s2;
}

// ---------------------------------------------------------------------------
// Flash attention: tf32 S-phase (unchanged) + fp16 PV phase (m16n8k16,
// C-layout==A-layout -> no shuffles; V staged transposed-packed half2).
// Block: 1 head x 128 q-rows, 8 warps x 16 rows. K-tile 64.
// ---------------------------------------------------------------------------
#define SK_LD 132
#define SVT_LD 136
#define SK_WORDS (64 * SK_LD)                 // 8448
#define SVT_WORDS (32 * SVT_LD)               // 4352
#define ATTN_SMEM ((SK_WORDS + SVT_WORDS) * 4)  // 51200 B

__global__ void __launch_bounds__(256, 1) attn_mma_kernel()
{
    extern __shared__ u32 smem[];
    u32* sK  = smem;                 // [64][SK_LD]  tf32
    u32* sVT = smem + SK_WORDS;      // [32 key-pairs][SVT_LD] half2 (d-major)

    const int t = threadIdx.x;
    const int lane = t & 31, wid = t >> 5;
    const int g = lane >> 2, tg = lane & 3;
    const int qt = 15 - blockIdx.x;          // heavy tiles first
    const int h  = blockIdx.y;
    const int kvh = h >> 3;
    const int qbase = qt * 128 + wid * 16;
    const int r0 = qbase + g, r1 = qbase + g + 8;

    // Q fragments (tf32) in registers
    u32 qf[16][4];
    const float* Qp = g_Q + (size_t)qbase * HIDDEN + h * HD;
    #pragma unroll
    for (int ks = 0; ks < 16; ks++) {
        qf[ks][0] = f2tf32(Qp[(size_t)g * HIDDEN + ks * 8 + tg]);
        qf[ks][1] = f2tf32(Qp[(size_t)(g + 8) * HIDDEN + ks * 8 + tg]);
        qf[ks][2] = f2tf32(Qp[(size_t)g * HIDDEN + ks * 8 + tg + 4]);
        qf[ks][3] = f2tf32(Qp[(size_t)(g + 8) * HIDDEN + ks * 8 + tg + 4]);
    }

    float o[16][4];
    #pragma unroll
    for (int n = 0; n < 16; n++)
        #pragma unroll
        for (int r = 0; r < 4; r++) o[n][r] = 0.f;
    float m0 = -1e30f, m1 = -1e30f, l0 = 0.f, l1 = 0.f;

    const int ntiles = 2 * qt + 2;

    for (int kt = 0; kt < ntiles; kt++) {
        __syncthreads();
        // ---- stage K tile (64x128) as tf32 ----
        #pragma unroll
        for (int p = 0; p < 8; p++) {
            const int idx = p * 256 + t;
            const int r = idx >> 5;
            const int c4 = (idx & 31) << 2;
            const float4 kk =
                *(const float4*)&g_K[(size_t)(kt * 64 + r) * KVW + kvh * HD + c4];
            u32* dk = sK + r * SK_LD + c4;
            dk[0] = f2tf32(kk.x); dk[1] = f2tf32(kk.y);
            dk[2] = f2tf32(kk.z); dk[3] = f2tf32(kk.w);
        }
        // ---- stage V tile transposed-packed: sVT[kp][d] = half2(V[2kp][d], V[2kp+1][d]) ----
        #pragma unroll
        for (int p = 0; p < 8; p++) {
            const int idx = p * 256 + t;
            const int kp = idx >> 6;             // 0..31
            const int d0 = (idx & 63) * 2;       // 0..126
            const size_t base = (size_t)(kt * 64 + 2 * kp) * KVW + kvh * HD + d0;
            const float2 v0 = *(const float2*)&g_V[base];        // key 2kp
            const float2 v1 = *(const float2*)&g_V[base + KVW];  // key 2kp+1
            u32 w0 = pack_h2(v0.x, v1.x);        // dim d0   (even key in lo)
            u32 w1 = pack_h2(v0.y, v1.y);        // dim d0+1
            *(uint2*)(sVT + kp * SVT_LD + d0) = make_uint2(w0, w1);
        }
        __syncthreads();

        if (kt * 64 > qbase + 15) continue;   // fully masked for this warp

        // ---- S = Q K^T (16 x 64), tf32 ----
        float c[8][4];
        #pragma unroll
        for (int j = 0; j < 8; j++)
            #pragma unroll
            for (int r = 0; r < 4; r++) c[j][r] = 0.f;

        #pragma unroll
        for (int ks = 0; ks < 16; ks++) {
            #pragma unroll
            for (int j = 0; j < 8; j++) {
                u32 bf[2];
                const u32* bb = sK + (j * 8 + g) * SK_LD + ks * 8 + tg;
                bf[0] = bb[0];
                bf[1] = bb[4];
                mma_tf32(c[j], qf[ks], bf);
            }
        }

        // ---- scale + causal mask ----
        const bool diag = (kt * 64 + 63 > qbase);
        #pragma unroll
        for (int j = 0; j < 8; j++) {
            const int key = kt * 64 + j * 8 + 2 * tg;
            c[j][0] *= ATT_SCALE; c[j][1] *= ATT_SCALE;
            c[j][2] *= ATT_SCALE; c[j][3] *= ATT_SCALE;
            if (diag) {
                if (key     > r0) c[j][0] = -1e30f;
                if (key + 1 > r0) c[j][1] = -1e30f;
                if (key     > r1) c[j][2] = -1e30f;
                if (key + 1 > r1) c[j][3] = -1e30f;
            }
        }

        // ---- online softmax ----
        float mx0 = m0, mx1 = m1;
        #pragma unroll
        for (int j = 0; j < 8; j++) {
            mx0 = fmaxf(mx0, fmaxf(c[j][0], c[j][1]));
            mx1 = fmaxf(mx1, fmaxf(c[j][2], c[j][3]));
        }
        mx0 = fmaxf(mx0, __shfl_xor_sync(0xffffffffu, mx0, 1));
        mx0 = fmaxf(mx0, __shfl_xor_sync(0xffffffffu, mx0, 2));
        mx1 = fmaxf(mx1, __shfl_xor_sync(0xffffffffu, mx1, 1));
        mx1 = fmaxf(mx1, __shfl_xor_sync(0xffffffffu, mx1, 2));
        const float corr0 = __expf(m0 - mx0);
        const float corr1 = __expf(m1 - mx1);
        m0 = mx0; m1 = mx1;
        l0 *= corr0; l1 *= corr1;
        #pragma unroll
        for (int n = 0; n < 16; n++) {
            o[n][0] *= corr0; o[n][1] *= corr0;
            o[n][2] *= corr1; o[n][3] *= corr1;
        }

        // ---- P = exp(S - m) packed to fp16 in-register;  O += P V (m16n8k16) ----
        float s0 = 0.f, s1 = 0.f;
        #pragma unroll
        for (int kg = 0; kg < 4; kg++) {
            const int j0 = kg * 2, j1 = kg * 2 + 1;
            const float e00a = __expf(c[j0][0] - m0);
            const float e01a = __expf(c[j0][1] - m0);
            const float e10a = __expf(c[j0][2] - m1);
            const float e11a = __expf(c[j0][3] - m1);
            const float e00b = __expf(c[j1][0] - m0);
            const float e01b = __expf(c[j1][1] - m0);
            const float e10b = __expf(c[j1][2] - m1);
            const float e11b = __expf(c[j1][3] - m1);
            s0 += e00a + e01a + e00b + e01b;
            s1 += e10a + e11a + e10b + e11b;

            u32 af[4];
            af[0] = pack_h2(e00a, e01a);   // row g,   keys kg*16 + 2tg, 2tg+1
            af[1] = pack_h2(e10a, e11a);   // row g+8
            af[2] = pack_h2(e00b, e01b);   // row g,   keys kg*16+8 + 2tg, 2tg+1
            af[3] = pack_h2(e10b, e11b);   // row g+8

            #pragma unroll
            for (int n = 0; n < 16; n++) {
                u32 bf[2];
                const u32* bb = sVT + (kg * 8 + tg) * SVT_LD + n * 8 + g;
                bf[0] = bb[0];
                bf[1] = bb[4 * SVT_LD];
                mma_f16(o[n], af, bf);
            }
        }
        s0 += __shfl_xor_sync(0xffffffffu, s0, 1);
        s0 += __shfl_xor_sync(0xffffffffu, s0, 2);
        s1 += __shfl_xor_sync(0xffffffffu, s1, 1);
        s1 += __shfl_xor_sync(0xffffffffu, s1, 2);
        l0 += s0; l1 += s1;
    }

    // ---- epilogue ----
    const float inv0 = 1.f / l0;
    const float inv1 = 1.f / l1;
    float* cp0 = g_C + (size_t)r0 * HIDDEN + h * HD;
    float* cp1 = g_C + (size_t)r1 * HIDDEN + h * HD;
    #pragma unroll
    for (int n = 0; n < 16; n++) {
        const int col = n * 8 + 2 * tg;
        *(float2*)(cp0 + col) = make_float2(o[n][0] * inv0, o[n][1] * inv0);
        *(float2*)(cp1 + col) = make_float2(o[n][2] * inv1, o[n][3] * inv1);
    }
}

// ---------------------------------------------------------------------------
extern "C" void kernel_launch(void* const* d_in, const int* in_sizes, int n_in,
                              void* d_out, int out_size)
{
    const float* hs   = (const float*)d_in[0];
    const float* cosT = (const float*)d_in[1];
    const float* sinT = (const float*)d_in[2];
    // d_in[3] = attention_mask (pure causal; applied analytically)
    const float* Wq = (const float*)d_in[4];
    const float* bq = (const float*)d_in[5];
    const float* Wk = (const float*)d_in[6];
    const float* bk = (const float*)d_in[7];
    const float* Wv = (const float*)d_in[8];
    const float* bv = (const float*)d_in[9];
    const float* Wo = (const float*)d_in[10];
    float* out = (float*)d_out;

    cudaFuncSetAttribute(mma_gemm_kernel,
                         cudaFuncAttributeMaxDynamicSharedMemorySize, G_SMEM);
    cudaFuncSetAttribute(attn_mma_kernel,
                         cudaFuncAttributeMaxDynamicSharedMemorySize, ATTN_SMEM);

    // fused QKV projection: blocks 0-15 -> Q, 16-17 -> K, 18-19 -> V
    mma_gemm_kernel<<<dim3(20, 16), 256, G_SMEM>>>(
        hs, Wq, Wk, Wv, bq, bk, bv, nullptr, 1);

    rope_kernel<<<(SEQ * NH  * 64 + 255) / 256, 256>>>(cosT, sinT, NH, 1);
    rope_kernel<<<(SEQ * NKV * 64 + 255) / 256, 256>>>(cosT, sinT, NKV, 0);

    attn_mma_kernel<<<dim3(16, 16), 256, ATTN_SMEM>>>();

    // O projection
    mma_gemm_kernel<<<dim3(16, 16), 256, G_SMEM>>>(
        g_C, Wo, nullptr, nullptr, nullptr, nullptr, nullptr, out, 0);
}

// round 11
// speedup vs baseline: 1.8861x; 1.8861x over previous
#include <cuda_runtime.h>

typedef unsigned int u32;

#define SEQ 2048
#define HIDDEN 2048
#define NH 16
#define NKV 2
#define HD 128
#define KVW (NKV*HD)          // 256
#define ATT_SCALE 0.08838834764831845f

// ---------------- scratch (no allocations allowed) ----------------
__device__ float g_Q[SEQ*HIDDEN];
__device__ float g_K[SEQ*KVW];
__device__ float g_V[SEQ*KVW];
__device__ float g_C[SEQ*HIDDEN];

// ---------------- helpers ----------------
__device__ __forceinline__ u32 f2tf32(float f) {
    u32 r;
    asm("cvt.rna.tf32.f32 %0, %1;" : "=r"(r) : "f"(f));
    return r;
}
__device__ __forceinline__ void mma_tf32(float* c, const u32* a, const u32* b) {
    asm volatile(
        "mma.sync.aligned.m16n8k8.row.col.f32.tf32.tf32.f32 "
        "{%0,%1,%2,%3}, {%4,%5,%6,%7}, {%8,%9}, {%0,%1,%2,%3};"
        : "+f"(c[0]), "+f"(c[1]), "+f"(c[2]), "+f"(c[3])
        : "r"(a[0]), "r"(a[1]), "r"(a[2]), "r"(a[3]),
          "r"(b[0]), "r"(b[1]));
}
__device__ __forceinline__ void mma_f16(float* c, const u32* a, const u32* b) {
    asm volatile(
        "mma.sync.aligned.m16n8k16.row.col.f32.f16.f16.f32 "
        "{%0,%1,%2,%3}, {%4,%5,%6,%7}, {%8,%9}, {%0,%1,%2,%3};"
        : "+f"(c[0]), "+f"(c[1]), "+f"(c[2]), "+f"(c[3])
        : "r"(a[0]), "r"(a[1]), "r"(a[2]), "r"(a[3]),
          "r"(b[0]), "r"(b[1]));
}
// pack two fp32 -> f16x2, 'lo' in low half (convention verified in R10)
__device__ __forceinline__ u32 pack_h2(float lo, float hi) {
    u32 r;
    asm("cvt.rn.f16x2.f32 %0, %1, %2;" : "=r"(r) : "f"(hi), "f"(lo));
    return r;
}

// ---------------------------------------------------------------------------
// fp16 mma.sync GEMM: C[M,N] = A[M,K] @ W[K,N] (+bias), fp32 accumulate.
// 128x128 block tile, 8 warps (2M x 4N -> 64x32 each), K-chunk 32 (= 2 ksteps
// of m16n8k16). Operands half2-packed along K. Double-buffered smem,
// one barrier per chunk, reg staging (NO cp.async).
// sA: [128 rows][20 u32 words]  word w = half2(A[k=2w], A[k=2w+1])
// sB: [16 k-pairs][136 u32]     sB[kp][n] = half2(W[2kp][n], W[2kp+1][n])
// mode 1: fused QKV (blocks 0-15 -> Q, 16-17 -> K, 18-19 -> V), mode 0: O-proj.
// ---------------------------------------------------------------------------
#define G_SA_LD 20
#define G_SB_LD 136
#define G_STAGE_A (128*G_SA_LD)              // 2560 words
#define G_STAGE (G_STAGE_A + 16*G_SB_LD)     // 4736 words
#define G_SMEM (2*G_STAGE*4)                 // 37888 B

__device__ __forceinline__ void gemm_stage_store(
    u32* buf, const float4* ar, const float2* br0, const float2* br1,
    int arow, int aseg, int bkp, int bcol)
{
    #pragma unroll
    for (int p = 0; p < 4; p++) {
        // A: row arow+32p, words aseg*2, aseg*2+1
        *(uint2*)(buf + (arow + p * 32) * G_SA_LD + aseg * 2) =
            make_uint2(pack_h2(ar[p].x, ar[p].y), pack_h2(ar[p].z, ar[p].w));
        // B: k-pair bkp+4p, cols bcol, bcol+1
        *(uint2*)(buf + G_STAGE_A + (bkp + p * 4) * G_SB_LD + bcol) =
            make_uint2(pack_h2(br0[p].x, br1[p].x), pack_h2(br0[p].y, br1[p].y));
    }
}

__global__ void __launch_bounds__(256) mma_gemm_kernel(
    const float* __restrict__ A_ext,
    const float* __restrict__ W0, const float* __restrict__ W1,
    const float* __restrict__ W2,
    const float* __restrict__ b0, const float* __restrict__ b1,
    const float* __restrict__ b2,
    float* __restrict__ outF, int mode)
{
    extern __shared__ u32 smg[];
    const int t = threadIdx.x;
    const int wid = t >> 5, lane = t & 31;
    const int warpM = wid & 1, warpN = wid >> 1;
    const int g = lane >> 2, tg = lane & 3;
    const int row0 = blockIdx.y * 128;

    const float* A; const float* W; const float* bias; float* C; int Nw; int col0;
    if (mode == 1) {
        A = A_ext;
        const int bn = blockIdx.x;
        if (bn < 16)      { W = W0; bias = b0; C = g_Q; Nw = HIDDEN; col0 = bn * 128; }
        else if (bn < 18) { W = W1; bias = b1; C = g_K; Nw = KVW;    col0 = (bn - 16) * 128; }
        else              { W = W2; bias = b2; C = g_V; Nw = KVW;    col0 = (bn - 18) * 128; }
    } else {
        A = g_C; W = W0; bias = nullptr; C = outF; Nw = HIDDEN; col0 = blockIdx.x * 128;
    }

    float c[4][4][4];
    #pragma unroll
    for (int i = 0; i < 4; i++)
        #pragma unroll
        for (int j = 0; j < 4; j++)
            #pragma unroll
            for (int r = 0; r < 4; r++) c[i][j][r] = 0.f;

    // staging coords
    const int arow = t >> 3;           // 0..31 (4 passes of +32)
    const int aseg = t & 7;            // float4 slot in 32-k chunk
    const int bkp  = t >> 6;           // 0..3  (4 passes of +4 k-pairs)
    const int bcol = (t & 63) * 2;     // 0..126

    const float* Ap  = A + (size_t)(row0 + arow) * HIDDEN + aseg * 4;
    const float* Bp0 = W + (size_t)(2 * bkp) * Nw + col0 + bcol;        // even k row
    const float* Bp1 = Bp0 + Nw;                                         // odd k row
    const size_t aRow32 = (size_t)32 * HIDDEN;
    const size_t bRow8  = (size_t)8 * Nw;       // +4 k-pairs
    const int NCH = HIDDEN >> 5;                // 64

    float4 ar[4]; float2 br0[4], br1[4];
    // chunk 0 -> regs -> buf0
    #pragma unroll
    for (int p = 0; p < 4; p++) {
        ar[p]  = *(const float4*)(Ap + p * aRow32);
        br0[p] = *(const float2*)(Bp0 + p * bRow8);
        br1[p] = *(const float2*)(Bp1 + p * bRow8);
    }
    gemm_stage_store(smg, ar, br0, br1, arow, aseg, bkp, bcol);
    // chunk 1 -> regs
    #pragma unroll
    for (int p = 0; p < 4; p++) {
        ar[p]  = *(const float4*)(Ap + 32 + p * aRow32);
        br0[p] = *(const float2*)(Bp0 + (size_t)32 * Nw + p * bRow8);
        br1[p] = *(const float2*)(Bp1 + (size_t)32 * Nw + p * bRow8);
    }

    const int bcolw = warpN * 32;

    for (int ch = 0; ch < NCH; ch++) {
        __syncthreads();   // all warps done with iter ch-1

        if (ch + 1 < NCH)
            gemm_stage_store(smg + ((ch + 1) & 1) * G_STAGE, ar, br0, br1,
                             arow, aseg, bkp, bcol);

        if (ch + 2 < NCH) {
            const int ko = (ch + 2) * 32;
            #pragma unroll
            for (int p = 0; p < 4; p++) {
                ar[p]  = *(const float4*)(Ap + ko + p * aRow32);
                br0[p] = *(const float2*)(Bp0 + (size_t)ko * Nw + p * bRow8);
                br1[p] = *(const float2*)(Bp1 + (size_t)ko * Nw + p * bRow8);
            }
        }

        const u32* sA = smg + (ch & 1) * G_STAGE;
        const u32* sB = sA + G_STAGE_A;
        const u32* sAw = sA + (warpM * 64) * G_SA_LD;

        #pragma unroll
        for (int ks = 0; ks < 2; ks++) {     // 2 ksteps of k=16
            const int kw = ks * 8;           // word offset in A row / k-pair row in B
            u32 af[4][4], bf[4][2];
            #pragma unroll
            for (int i = 0; i < 4; i++) {
                const u32* base = sAw + (i * 16 + g) * G_SA_LD + kw + tg;
                af[i][0] = base[0];
                af[i][1] = base[8 * G_SA_LD];
                af[i][2] = base[4];
                af[i][3] = base[8 * G_SA_LD + 4];
            }
            #pragma unroll
            for (int j = 0; j < 4; j++) {
                const u32* base = sB + (kw + tg) * G_SB_LD + bcolw + j * 8 + g;
                bf[j][0] = base[0];
                bf[j][1] = base[4 * G_SB_LD];
            }
            #pragma unroll
            for (int i = 0; i < 4; i++)
                #pragma unroll
                for (int j = 0; j < 4; j++)
                    mma_f16(c[i][j], af[i], bf[j]);
        }
    }

    // epilogue (C-fragment layout identical to k8 case)
    #pragma unroll
    for (int i = 0; i < 4; i++) {
        const int r0e = row0 + warpM * 64 + i * 16 + g;
        #pragma unroll
        for (int j = 0; j < 4; j++) {
            const int col = col0 + warpN * 32 + j * 8 + 2 * tg;
            float bb0 = 0.f, bb1 = 0.f;
            if (bias) { bb0 = bias[col]; bb1 = bias[col + 1]; }
            *(float2*)(C + (size_t)r0e * Nw + col) =
                make_float2(c[i][j][0] + bb0, c[i][j][1] + bb1);
            *(float2*)(C + (size_t)(r0e + 8) * Nw + col) =
                make_float2(c[i][j][2] + bb0, c[i][j][3] + bb1);
        }
    }
}

// ---------------------------------------------------------------------------
// RoPE in place (round-4 verbatim)
// ---------------------------------------------------------------------------
__global__ void rope_kernel(const float* __restrict__ cosT,
                            const float* __restrict__ sinT,
                            int nheads, int which)
{
    float* X = which ? g_Q : g_K;
    const int idx = blockIdx.x * blockDim.x + threadIdx.x;
    const int total = SEQ * nheads * 64;
    if (idx >= total) return;
    const int d = idx & 63;
    const int h = (idx >> 6) % nheads;
    const int s = idx / (64 * nheads);

    const float c1 = cosT[s * HD + d];
    const float s1 = sinT[s * HD + d];
    const float c2 = cosT[s * HD + d + 64];
    const float s2 = sinT[s * HD + d + 64];

    float* p = X + (size_t)s * (nheads * HD) + h * HD + d;
    const float x1 = p[0];
    const float x2 = p[64];
    p[0]  = x1 * c1 - x2 * s1;
    p[64] = x2 * c2 + x1 * s2;
}

// ---------------------------------------------------------------------------
// mma.sync tf32 flash attention (round-8 verbatim, proven at 206us)
// ---------------------------------------------------------------------------
#define SK_LD 132
#define SV_LD 136
#define SK_WORDS (64 * SK_LD)
#define SV_WORDS (64 * SV_LD)
#define ATTN_SMEM ((SK_WORDS + SV_WORDS) * 4)

__global__ void __launch_bounds__(256, 1) attn_mma_kernel()
{
    extern __shared__ u32 smem[];
    u32* sK = smem;                 // [64][SK_LD]
    u32* sV = smem + SK_WORDS;      // [64][SV_LD]

    const int t = threadIdx.x;
    const int lane = t & 31, wid = t >> 5;
    const int g = lane >> 2, tg = lane & 3;
    const int qt = 15 - blockIdx.x;          // heavy tiles first
    const int h  = blockIdx.y;
    const int kvh = h >> 3;
    const int qbase = qt * 128 + wid * 16;
    const int r0 = qbase + g, r1 = qbase + g + 8;

    // Q fragments (tf32) in registers: rows r0/r1, all 128 dims
    u32 qf[16][4];
    const float* Qp = g_Q + (size_t)qbase * HIDDEN + h * HD;
    #pragma unroll
    for (int ks = 0; ks < 16; ks++) {
        qf[ks][0] = f2tf32(Qp[(size_t)g * HIDDEN + ks * 8 + tg]);
        qf[ks][1] = f2tf32(Qp[(size_t)(g + 8) * HIDDEN + ks * 8 + tg]);
        qf[ks][2] = f2tf32(Qp[(size_t)g * HIDDEN + ks * 8 + tg + 4]);
        qf[ks][3] = f2tf32(Qp[(size_t)(g + 8) * HIDDEN + ks * 8 + tg + 4]);
    }

    float o[16][4];
    #pragma unroll
    for (int n = 0; n < 16; n++)
        #pragma unroll
        for (int r = 0; r < 4; r++) o[n][r] = 0.f;
    float m0 = -1e30f, m1 = -1e30f, l0 = 0.f, l1 = 0.f;

    const int ntiles = 2 * qt + 2;

    for (int kt = 0; kt < ntiles; kt++) {
        __syncthreads();
        // stage K/V tile (64x128) as tf32
        #pragma unroll
        for (int p = 0; p < 8; p++) {
            const int idx = p * 256 + t;
            const int r = idx >> 5;
            const int c4 = (idx & 31) << 2;
            const size_t goff = (size_t)(kt * 64 + r) * KVW + kvh * HD + c4;
            float4 kk = *(const float4*)&g_K[goff];
            float4 vv = *(const float4*)&g_V[goff];
            u32* dk = sK + r * SK_LD + c4;
            dk[0] = f2tf32(kk.x); dk[1] = f2tf32(kk.y);
            dk[2] = f2tf32(kk.z); dk[3] = f2tf32(kk.w);
            u32* dv = sV + r * SV_LD + c4;
            dv[0] = f2tf32(vv.x); dv[1] = f2tf32(vv.y);
            dv[2] = f2tf32(vv.z); dv[3] = f2tf32(vv.w);
        }
        __syncthreads();

        if (kt * 64 > qbase + 15) continue;   // fully masked for this warp

        // ---- S = Q K^T (16 x 64) ----
        float c[8][4];
        #pragma unroll
        for (int j = 0; j < 8; j++)
            #pragma unroll
            for (int r = 0; r < 4; r++) c[j][r] = 0.f;

        #pragma unroll
        for (int ks = 0; ks < 16; ks++) {
            #pragma unroll
            for (int j = 0; j < 8; j++) {
                u32 bf[2];
                const u32* bb = sK + (j * 8 + g) * SK_LD + ks * 8 + tg;
                bf[0] = bb[0];
                bf[1] = bb[4];
                mma_tf32(c[j], qf[ks], bf);
            }
        }

        // ---- scale + causal mask ----
        const bool diag = (kt * 64 + 63 > qbase);
        #pragma unroll
        for (int j = 0; j < 8; j++) {
            const int key = kt * 64 + j * 8 + 2 * tg;
            c[j][0] *= ATT_SCALE; c[j][1] *= ATT_SCALE;
            c[j][2] *= ATT_SCALE; c[j][3] *= ATT_SCALE;
            if (diag) {
                if (key     > r0) c[j][0] = -1e30f;
                if (key + 1 > r0) c[j][1] = -1e30f;
                if (key     > r1) c[j][2] = -1e30f;
                if (key + 1 > r1) c[j][3] = -1e30f;
            }
        }

        // ---- online softmax ----
        float mx0 = m0, mx1 = m1;
        #pragma unroll
        for (int j = 0; j < 8; j++) {
            mx0 = fmaxf(mx0, fmaxf(c[j][0], c[j][1]));
            mx1 = fmaxf(mx1, fmaxf(c[j][2], c[j][3]));
        }
        mx0 = fmaxf(mx0, __shfl_xor_sync(0xffffffffu, mx0, 1));
        mx0 = fmaxf(mx0, __shfl_xor_sync(0xffffffffu, mx0, 2));
        mx1 = fmaxf(mx1, __shfl_xor_sync(0xffffffffu, mx1, 1));
        mx1 = fmaxf(mx1, __shfl_xor_sync(0xffffffffu, mx1, 2));
        const float corr0 = __expf(m0 - mx0);
        const float corr1 = __expf(m1 - mx1);
        m0 = mx0; m1 = mx1;
        l0 *= corr0; l1 *= corr1;
        #pragma unroll
        for (int n = 0; n < 16; n++) {
            o[n][0] *= corr0; o[n][1] *= corr0;
            o[n][2] *= corr1; o[n][3] *= corr1;
        }

        // ---- P = exp(S - m);  O += P V ----
        float s0 = 0.f, s1 = 0.f;
        const int srcA = (lane & ~3) | (tg >> 1);
        const int srcB = srcA + 2;
        const bool odd = tg & 1;
        #pragma unroll
        for (int kb = 0; kb < 8; kb++) {
            const float e00 = __expf(c[kb][0] - m0);
            const float e01 = __expf(c[kb][1] - m0);
            const float e10 = __expf(c[kb][2] - m1);
            const float e11 = __expf(c[kb][3] - m1);
            s0 += e00 + e01; s1 += e10 + e11;

            const float f00 = __shfl_sync(0xffffffffu, e00, srcA);
            const float f01 = __shfl_sync(0xffffffffu, e01, srcA);
            const float f02 = __shfl_sync(0xffffffffu, e00, srcB);
            const float f03 = __shfl_sync(0xffffffffu, e01, srcB);
            const float f10 = __shfl_sync(0xffffffffu, e10, srcA);
            const float f11 = __shfl_sync(0xffffffffu, e11, srcA);
            const float f12 = __shfl_sync(0xffffffffu, e10, srcB);
            const float f13 = __shfl_sync(0xffffffffu, e11, srcB);
            u32 af[4];
            af[0] = f2tf32(odd ? f01 : f00);
            af[1] = f2tf32(odd ? f11 : f10);
            af[2] = f2tf32(odd ? f03 : f02);
            af[3] = f2tf32(odd ? f13 : f12);

            #pragma unroll
            for (int n = 0; n < 16; n++) {
                u32 bf[2];
                const u32* bb = sV + (kb * 8 + tg) * SV_LD + n * 8 + g;
                bf[0] = bb[0];
                bf[1] = bb[4 * SV_LD];
                mma_tf32(o[n], af, bf);
            }
        }
        s0 += __shfl_xor_sync(0xffffffffu, s0, 1);
        s0 += __shfl_xor_sync(0xffffffffu, s0, 2);
        s1 += __shfl_xor_sync(0xffffffffu, s1, 1);
        s1 += __shfl_xor_sync(0xffffffffu, s1, 2);
        l0 += s0; l1 += s1;
    }

    // ---- epilogue ----
    const float inv0 = 1.f / l0;
    const float inv1 = 1.f / l1;
    float* cp0 = g_C + (size_t)r0 * HIDDEN + h * HD;
    float* cp1 = g_C + (size_t)r1 * HIDDEN + h * HD;
    #pragma unroll
    for (int n = 0; n < 16; n++) {
        const int col = n * 8 + 2 * tg;
        *(float2*)(cp0 + col) = make_float2(o[n][0] * inv0, o[n][1] * inv0);
        *(float2*)(cp1 + col) = make_float2(o[n][2] * inv1, o[n][3] * inv1);
    }
}

// ---------------------------------------------------------------------------
extern "C" void kernel_launch(void* const* d_in, const int* in_sizes, int n_in,
                              void* d_out, int out_size)
{
    const float* hs   = (const float*)d_in[0];
    const float* cosT = (const float*)d_in[1];
    const float* sinT = (const float*)d_in[2];
    // d_in[3] = attention_mask (pure causal; applied analytically)
    const float* Wq = (const float*)d_in[4];
    const float* bq = (const float*)d_in[5];
    const float* Wk = (const float*)d_in[6];
    const float* bk = (const float*)d_in[7];
    const float* Wv = (const float*)d_in[8];
    const float* bv = (const float*)d_in[9];
    const float* Wo = (const float*)d_in[10];
    float* out = (float*)d_out;

    cudaFuncSetAttribute(mma_gemm_kernel,
                         cudaFuncAttributeMaxDynamicSharedMemorySize, G_SMEM);
    cudaFuncSetAttribute(attn_mma_kernel,
                         cudaFuncAttributeMaxDynamicSharedMemorySize, ATTN_SMEM);

    // fused QKV projection: blocks 0-15 -> Q, 16-17 -> K, 18-19 -> V
    mma_gemm_kernel<<<dim3(20, 16), 256, G_SMEM>>>(
        hs, Wq, Wk, Wv, bq, bk, bv, nullptr, 1);

    rope_kernel<<<(SEQ * NH  * 64 + 255) / 256, 256>>>(cosT, sinT, NH, 1);
    rope_kernel<<<(SEQ * NKV * 64 + 255) / 256, 256>>>(cosT, sinT, NKV, 0);

    attn_mma_kernel<<<dim3(16, 16), 256, ATTN_SMEM>>>();

    // O projection
    mma_gemm_kernel<<<dim3(16, 16), 256, G_SMEM>>>(
        g_C, Wo, nullptr, nullptr, nullptr, nullptr, nullptr, out, 0);
}

// round 12
// speedup vs baseline: 1.9231x; 1.0196x over previous
#include <cuda_runtime.h>

typedef unsigned int u32;

#define SEQ 2048
#define HIDDEN 2048
#define NH 16
#define NKV 2
#define HD 128
#define KVW (NKV*HD)          // 256
#define ATT_SCALE 0.08838834764831845f

// ---------------- scratch (no allocations allowed) ----------------
__device__ float g_Q[SEQ*HIDDEN];
__device__ float g_K[SEQ*KVW];
__device__ float g_V[SEQ*KVW];
__device__ float g_C[SEQ*HIDDEN];

// ---------------- helpers ----------------
__device__ __forceinline__ u32 f2tf32(float f) {
    u32 r;
    asm("cvt.rna.tf32.f32 %0, %1;" : "=r"(r) : "f"(f));
    return r;
}
__device__ __forceinline__ void mma_tf32(float* c, const u32* a, const u32* b) {
    asm volatile(
        "mma.sync.aligned.m16n8k8.row.col.f32.tf32.tf32.f32 "
        "{%0,%1,%2,%3}, {%4,%5,%6,%7}, {%8,%9}, {%0,%1,%2,%3};"
        : "+f"(c[0]), "+f"(c[1]), "+f"(c[2]), "+f"(c[3])
        : "r"(a[0]), "r"(a[1]), "r"(a[2]), "r"(a[3]),
          "r"(b[0]), "r"(b[1]));
}
__device__ __forceinline__ void mma_f16(float* c, const u32* a, const u32* b) {
    asm volatile(
        "mma.sync.aligned.m16n8k16.row.col.f32.f16.f16.f32 "
        "{%0,%1,%2,%3}, {%4,%5,%6,%7}, {%8,%9}, {%0,%1,%2,%3};"
        : "+f"(c[0]), "+f"(c[1]), "+f"(c[2]), "+f"(c[3])
        : "r"(a[0]), "r"(a[1]), "r"(a[2]), "r"(a[3]),
          "r"(b[0]), "r"(b[1]));
}
// pack two fp32 -> f16x2, 'lo' in low half (convention verified in R10)
__device__ __forceinline__ u32 pack_h2(float lo, float hi) {
    u32 r;
    asm("cvt.rn.f16x2.f32 %0, %1, %2;" : "=r"(r) : "f"(hi), "f"(lo));
    return r;
}

// ---------------------------------------------------------------------------
// fp16 mma.sync GEMM (round-11 verbatim, proven): 128x128 tile, 8 warps,
// K-chunk 32 (2 ksteps of m16n8k16), double-buffered smem, reg staging.
// ---------------------------------------------------------------------------
#define G_SA_LD 20
#define G_SB_LD 136
#define G_STAGE_A (128*G_SA_LD)              // 2560 words
#define G_STAGE (G_STAGE_A + 16*G_SB_LD)     // 4736 words
#define G_SMEM (2*G_STAGE*4)                 // 37888 B

__device__ __forceinline__ void gemm_stage_store(
    u32* buf, const float4* ar, const float2* br0, const float2* br1,
    int arow, int aseg, int bkp, int bcol)
{
    #pragma unroll
    for (int p = 0; p < 4; p++) {
        *(uint2*)(buf + (arow + p * 32) * G_SA_LD + aseg * 2) =
            make_uint2(pack_h2(ar[p].x, ar[p].y), pack_h2(ar[p].z, ar[p].w));
        *(uint2*)(buf + G_STAGE_A + (bkp + p * 4) * G_SB_LD + bcol) =
            make_uint2(pack_h2(br0[p].x, br1[p].x), pack_h2(br0[p].y, br1[p].y));
    }
}

__global__ void __launch_bounds__(256) mma_gemm_kernel(
    const float* __restrict__ A_ext,
    const float* __restrict__ W0, const float* __restrict__ W1,
    const float* __restrict__ W2,
    const float* __restrict__ b0, const float* __restrict__ b1,
    const float* __restrict__ b2,
    float* __restrict__ outF, int mode)
{
    extern __shared__ u32 smg[];
    const int t = threadIdx.x;
    const int wid = t >> 5, lane = t & 31;
    const int warpM = wid & 1, warpN = wid >> 1;
    const int g = lane >> 2, tg = lane & 3;
    const int row0 = blockIdx.y * 128;

    const float* A; const float* W; const float* bias; float* C; int Nw; int col0;
    if (mode == 1) {
        A = A_ext;
        const int bn = blockIdx.x;
        if (bn < 16)      { W = W0; bias = b0; C = g_Q; Nw = HIDDEN; col0 = bn * 128; }
        else if (bn < 18) { W = W1; bias = b1; C = g_K; Nw = KVW;    col0 = (bn - 16) * 128; }
        else              { W = W2; bias = b2; C = g_V; Nw = KVW;    col0 = (bn - 18) * 128; }
    } else {
        A = g_C; W = W0; bias = nullptr; C = outF; Nw = HIDDEN; col0 = blockIdx.x * 128;
    }

    float c[4][4][4];
    #pragma unroll
    for (int i = 0; i < 4; i++)
        #pragma unroll
        for (int j = 0; j < 4; j++)
            #pragma unroll
            for (int r = 0; r < 4; r++) c[i][j][r] = 0.f;

    const int arow = t >> 3;
    const int aseg = t & 7;
    const int bkp  = t >> 6;
    const int bcol = (t & 63) * 2;

    const float* Ap  = A + (size_t)(row0 + arow) * HIDDEN + aseg * 4;
    const float* Bp0 = W + (size_t)(2 * bkp) * Nw + col0 + bcol;
    const float* Bp1 = Bp0 + Nw;
    const size_t aRow32 = (size_t)32 * HIDDEN;
    const size_t bRow8  = (size_t)8 * Nw;
    const int NCH = HIDDEN >> 5;

    float4 ar[4]; float2 br0[4], br1[4];
    #pragma unroll
    for (int p = 0; p < 4; p++) {
        ar[p]  = *(const float4*)(Ap + p * aRow32);
        br0[p] = *(const float2*)(Bp0 + p * bRow8);
        br1[p] = *(const float2*)(Bp1 + p * bRow8);
    }
    gemm_stage_store(smg, ar, br0, br1, arow, aseg, bkp, bcol);
    #pragma unroll
    for (int p = 0; p < 4; p++) {
        ar[p]  = *(const float4*)(Ap + 32 + p * aRow32);
        br0[p] = *(const float2*)(Bp0 + (size_t)32 * Nw + p * bRow8);
        br1[p] = *(const float2*)(Bp1 + (size_t)32 * Nw + p * bRow8);
    }

    const int bcolw = warpN * 32;

    for (int ch = 0; ch < NCH; ch++) {
        __syncthreads();

        if (ch + 1 < NCH)
            gemm_stage_store(smg + ((ch + 1) & 1) * G_STAGE, ar, br0, br1,
                             arow, aseg, bkp, bcol);

        if (ch + 2 < NCH) {
            const int ko = (ch + 2) * 32;
            #pragma unroll
            for (int p = 0; p < 4; p++) {
                ar[p]  = *(const float4*)(Ap + ko + p * aRow32);
                br0[p] = *(const float2*)(Bp0 + (size_t)ko * Nw + p * bRow8);
                br1[p] = *(const float2*)(Bp1 + (size_t)ko * Nw + p * bRow8);
            }
        }

        const u32* sA = smg + (ch & 1) * G_STAGE;
        const u32* sB = sA + G_STAGE_A;
        const u32* sAw = sA + (warpM * 64) * G_SA_LD;

        #pragma unroll
        for (int ks = 0; ks < 2; ks++) {
            const int kw = ks * 8;
            u32 af[4][4], bf[4][2];
            #pragma unroll
            for (int i = 0; i < 4; i++) {
                const u32* base = sAw + (i * 16 + g) * G_SA_LD + kw + tg;
                af[i][0] = base[0];
                af[i][1] = base[8 * G_SA_LD];
                af[i][2] = base[4];
                af[i][3] = base[8 * G_SA_LD + 4];
            }
            #pragma unroll
            for (int j = 0; j < 4; j++) {
                const u32* base = sB + (kw + tg) * G_SB_LD + bcolw + j * 8 + g;
                bf[j][0] = base[0];
                bf[j][1] = base[4 * G_SB_LD];
            }
            #pragma unroll
            for (int i = 0; i < 4; i++)
                #pragma unroll
                for (int j = 0; j < 4; j++)
                    mma_f16(c[i][j], af[i], bf[j]);
        }
    }

    #pragma unroll
    for (int i = 0; i < 4; i++) {
        const int r0e = row0 + warpM * 64 + i * 16 + g;
        #pragma unroll
        for (int j = 0; j < 4; j++) {
            const int col = col0 + warpN * 32 + j * 8 + 2 * tg;
            float bb0 = 0.f, bb1 = 0.f;
            if (bias) { bb0 = bias[col]; bb1 = bias[col + 1]; }
            *(float2*)(C + (size_t)r0e * Nw + col) =
                make_float2(c[i][j][0] + bb0, c[i][j][1] + bb1);
            *(float2*)(C + (size_t)(r0e + 8) * Nw + col) =
                make_float2(c[i][j][2] + bb0, c[i][j][3] + bb1);
        }
    }
}

// ---------------------------------------------------------------------------
// RoPE in place (round-4 verbatim)
// ---------------------------------------------------------------------------
__global__ void rope_kernel(const float* __restrict__ cosT,
                            const float* __restrict__ sinT,
                            int nheads, int which)
{
    float* X = which ? g_Q : g_K;
    const int idx = blockIdx.x * blockDim.x + threadIdx.x;
    const int total = SEQ * nheads * 64;
    if (idx >= total) return;
    const int d = idx & 63;
    const int h = (idx >> 6) % nheads;
    const int s = idx / (64 * nheads);

    const float c1 = cosT[s * HD + d];
    const float s1 = sinT[s * HD + d];
    const float c2 = cosT[s * HD + d + 64];
    const float s2 = sinT[s * HD + d + 64];

    float* p = X + (size_t)s * (nheads * HD) + h * HD + d;
    const float x1 = p[0];
    const float x2 = p[64];
    p[0]  = x1 * c1 - x2 * s1;
    p[64] = x2 * c2 + x1 * s2;
}

// ---------------------------------------------------------------------------
// mma.sync tf32 flash attention — warp math round-8 verbatim; CTA split to
// 128 threads (4 warps x 16 q-rows = 64 q-rows), grid 32 qtiles x 16 heads,
// 2 CTAs/SM for latency overlap.
// ---------------------------------------------------------------------------
#define SK_LD 132
#define SV_LD 136
#define SK_WORDS (64 * SK_LD)
#define SV_WORDS (64 * SV_LD)
#define ATTN_SMEM ((SK_WORDS + SV_WORDS) * 4)

__global__ void __launch_bounds__(128) attn_mma_kernel()
{
    extern __shared__ u32 smem[];
    u32* sK = smem;                 // [64][SK_LD]
    u32* sV = smem + SK_WORDS;      // [64][SV_LD]

    const int t = threadIdx.x;
    const int lane = t & 31, wid = t >> 5;          // wid 0..3
    const int g = lane >> 2, tg = lane & 3;
    const int qt = 31 - blockIdx.x;                 // heavy tiles first (0..31)
    const int h  = blockIdx.y;
    const int kvh = h >> 3;
    const int qbase = qt * 64 + wid * 16;
    const int r0 = qbase + g, r1 = qbase + g + 8;

    // Q fragments (tf32) in registers: rows r0/r1, all 128 dims
    u32 qf[16][4];
    const float* Qp = g_Q + (size_t)qbase * HIDDEN + h * HD;
    #pragma unroll
    for (int ks = 0; ks < 16; ks++) {
        qf[ks][0] = f2tf32(Qp[(size_t)g * HIDDEN + ks * 8 + tg]);
        qf[ks][1] = f2tf32(Qp[(size_t)(g + 8) * HIDDEN + ks * 8 + tg]);
        qf[ks][2] = f2tf32(Qp[(size_t)g * HIDDEN + ks * 8 + tg + 4]);
        qf[ks][3] = f2tf32(Qp[(size_t)(g + 8) * HIDDEN + ks * 8 + tg + 4]);
    }

    float o[16][4];
    #pragma unroll
    for (int n = 0; n < 16; n++)
        #pragma unroll
        for (int r = 0; r < 4; r++) o[n][r] = 0.f;
    float m0 = -1e30f, m1 = -1e30f, l0 = 0.f, l1 = 0.f;

    const int ntiles = qt + 1;                      // 64-key tiles up to diagonal

    for (int kt = 0; kt < ntiles; kt++) {
        __syncthreads();
        // stage K/V tile (64x128) as tf32 — 128 threads, 16 passes
        #pragma unroll
        for (int p = 0; p < 16; p++) {
            const int idx = p * 128 + t;
            const int r = idx >> 5;
            const int c4 = (idx & 31) << 2;
            const size_t goff = (size_t)(kt * 64 + r) * KVW + kvh * HD + c4;
            float4 kk = *(const float4*)&g_K[goff];
            float4 vv = *(const float4*)&g_V[goff];
            u32* dk = sK + r * SK_LD + c4;
            dk[0] = f2tf32(kk.x); dk[1] = f2tf32(kk.y);
            dk[2] = f2tf32(kk.z); dk[3] = f2tf32(kk.w);
            u32* dv = sV + r * SV_LD + c4;
            dv[0] = f2tf32(vv.x); dv[1] = f2tf32(vv.y);
            dv[2] = f2tf32(vv.z); dv[3] = f2tf32(vv.w);
        }
        __syncthreads();

        if (kt * 64 > qbase + 15) continue;   // fully masked for this warp

        // ---- S = Q K^T (16 x 64) ----
        float c[8][4];
        #pragma unroll
        for (int j = 0; j < 8; j++)
            #pragma unroll
            for (int r = 0; r < 4; r++) c[j][r] = 0.f;

        #pragma unroll
        for (int ks = 0; ks < 16; ks++) {
            #pragma unroll
            for (int j = 0; j < 8; j++) {
                u32 bf[2];
                const u32* bb = sK + (j * 8 + g) * SK_LD + ks * 8 + tg;
                bf[0] = bb[0];
                bf[1] = bb[4];
                mma_tf32(c[j], qf[ks], bf);
            }
        }

        // ---- scale + causal mask ----
        const bool diag = (kt * 64 + 63 > qbase);
        #pragma unroll
        for (int j = 0; j < 8; j++) {
            const int key = kt * 64 + j * 8 + 2 * tg;
            c[j][0] *= ATT_SCALE; c[j][1] *= ATT_SCALE;
            c[j][2] *= ATT_SCALE; c[j][3] *= ATT_SCALE;
            if (diag) {
                if (key     > r0) c[j][0] = -1e30f;
                if (key + 1 > r0) c[j][1] = -1e30f;
                if (key     > r1) c[j][2] = -1e30f;
                if (key + 1 > r1) c[j][3] = -1e30f;
            }
        }

        // ---- online softmax ----
        float mx0 = m0, mx1 = m1;
        #pragma unroll
        for (int j = 0; j < 8; j++) {
            mx0 = fmaxf(mx0, fmaxf(c[j][0], c[j][1]));
            mx1 = fmaxf(mx1, fmaxf(c[j][2], c[j][3]));
        }
        mx0 = fmaxf(mx0, __shfl_xor_sync(0xffffffffu, mx0, 1));
        mx0 = fmaxf(mx0, __shfl_xor_sync(0xffffffffu, mx0, 2));
        mx1 = fmaxf(mx1, __shfl_xor_sync(0xffffffffu, mx1, 1));
        mx1 = fmaxf(mx1, __shfl_xor_sync(0xffffffffu, mx1, 2));
        const float corr0 = __expf(m0 - mx0);
        const float corr1 = __expf(m1 - mx1);
        m0 = mx0; m1 = mx1;
        l0 *= corr0; l1 *= corr1;
        #pragma unroll
        for (int n = 0; n < 16; n++) {
            o[n][0] *= corr0; o[n][1] *= corr0;
            o[n][2] *= corr1; o[n][3] *= corr1;
        }

        // ---- P = exp(S - m);  O += P V ----
        float s0 = 0.f, s1 = 0.f;
        const int srcA = (lane & ~3) | (tg >> 1);
        const int srcB = srcA + 2;
        const bool odd = tg & 1;
        #pragma unroll
        for (int kb = 0; kb < 8; kb++) {
            const float e00 = __expf(c[kb][0] - m0);
            const float e01 = __expf(c[kb][1] - m0);
            const float e10 = __expf(c[kb][2] - m1);
            const float e11 = __expf(c[kb][3] - m1);
            s0 += e00 + e01; s1 += e10 + e11;

            const float f00 = __shfl_sync(0xffffffffu, e00, srcA);
            const float f01 = __shfl_sync(0xffffffffu, e01, srcA);
            const float f02 = __shfl_sync(0xffffffffu, e00, srcB);
            const float f03 = __shfl_sync(0xffffffffu, e01, srcB);
            const float f10 = __shfl_sync(0xffffffffu, e10, srcA);
            const float f11 = __shfl_sync(0xffffffffu, e11, srcA);
            const float f12 = __shfl_sync(0xffffffffu, e10, srcB);
            const float f13 = __shfl_sync(0xffffffffu, e11, srcB);
            u32 af[4];
            af[0] = f2tf32(odd ? f01 : f00);
            af[1] = f2tf32(odd ? f11 : f10);
            af[2] = f2tf32(odd ? f03 : f02);
            af[3] = f2tf32(odd ? f13 : f12);

            #pragma unroll
            for (int n = 0; n < 16; n++) {
                u32 bf[2];
                const u32* bb = sV + (kb * 8 + tg) * SV_LD + n * 8 + g;
                bf[0] = bb[0];
                bf[1] = bb[4 * SV_LD];
                mma_tf32(o[n], af, bf);
            }
        }
        s0 += __shfl_xor_sync(0xffffffffu, s0, 1);
        s0 += __shfl_xor_sync(0xffffffffu, s0, 2);
        s1 += __shfl_xor_sync(0xffffffffu, s1, 1);
        s1 += __shfl_xor_sync(0xffffffffu, s1, 2);
        l0 += s0; l1 += s1;
    }

    // ---- epilogue ----
    const float inv0 = 1.f / l0;
    const float inv1 = 1.f / l1;
    float* cp0 = g_C + (size_t)r0 * HIDDEN + h * HD;
    float* cp1 = g_C + (size_t)r1 * HIDDEN + h * HD;
    #pragma unroll
    for (int n = 0; n < 16; n++) {
        const int col = n * 8 + 2 * tg;
        *(float2*)(cp0 + col) = make_float2(o[n][0] * inv0, o[n][1] * inv0);
        *(float2*)(cp1 + col) = make_float2(o[n][2] * inv1, o[n][3] * inv1);
    }
}

// ---------------------------------------------------------------------------
extern "C" void kernel_launch(void* const* d_in, const int* in_sizes, int n_in,
                              void* d_out, int out_size)
{
    const float* hs   = (const float*)d_in[0];
    const float* cosT = (const float*)d_in[1];
    const float* sinT = (const float*)d_in[2];
    // d_in[3] = attention_mask (pure causal; applied analytically)
    const float* Wq = (const float*)d_in[4];
    const float* bq = (const float*)d_in[5];
    const float* Wk = (const float*)d_in[6];
    const float* bk = (const float*)d_in[7];
    const float* Wv = (const float*)d_in[8];
    const float* bv = (const float*)d_in[9];
    const float* Wo = (const float*)d_in[10];
    float* out = (float*)d_out;

    cudaFuncSetAttribute(mma_gemm_kernel,
                         cudaFuncAttributeMaxDynamicSharedMemorySize, G_SMEM);
    cudaFuncSetAttribute(attn_mma_kernel,
                         cudaFuncAttributeMaxDynamicSharedMemorySize, ATTN_SMEM);

    // fused QKV projection: blocks 0-15 -> Q, 16-17 -> K, 18-19 -> V
    mma_gemm_kernel<<<dim3(20, 16), 256, G_SMEM>>>(
        hs, Wq, Wk, Wv, bq, bk, bv, nullptr, 1);

    rope_kernel<<<(SEQ * NH  * 64 + 255) / 256, 256>>>(cosT, sinT, NH, 1);
    rope_kernel<<<(SEQ * NKV * 64 + 255) / 256, 256>>>(cosT, sinT, NKV, 0);

    attn_mma_kernel<<<dim3(32, 16), 128, ATTN_SMEM>>>();

    // O projection
    mma_gemm_kernel<<<dim3(16, 16), 256, G_SMEM>>>(
        g_C, Wo, nullptr, nullptr, nullptr, nullptr, nullptr, out, 0);
}

// round 13
// speedup vs baseline: 2.2838x; 1.1876x over previous
#include <cuda_runtime.h>

typedef unsigned int u32;

#define SEQ 2048
#define HIDDEN 2048
#define NH 16
#define NKV 2
#define HD 128
#define KVW (NKV*HD)          // 256
#define ATT_SCALE 0.08838834764831845f

// ---------------- scratch (no allocations allowed) ----------------
__device__ float g_Q[SEQ*HIDDEN];
__device__ float g_K[SEQ*KVW];
__device__ float g_V[SEQ*KVW];
__device__ float g_C[SEQ*HIDDEN];

// ---------------- helpers ----------------
__device__ __forceinline__ u32 f2tf32(float f) {
    u32 r;
    asm("cvt.rna.tf32.f32 %0, %1;" : "=r"(r) : "f"(f));
    return r;
}
__device__ __forceinline__ void mma_f16(float* c, const u32* a, const u32* b) {
    asm volatile(
        "mma.sync.aligned.m16n8k16.row.col.f32.f16.f16.f32 "
        "{%0,%1,%2,%3}, {%4,%5,%6,%7}, {%8,%9}, {%0,%1,%2,%3};"
        : "+f"(c[0]), "+f"(c[1]), "+f"(c[2]), "+f"(c[3])
        : "r"(a[0]), "r"(a[1]), "r"(a[2]), "r"(a[3]),
          "r"(b[0]), "r"(b[1]));
}
// pack two fp32 -> f16x2, 'lo' in low half (convention verified in R10/R11)
__device__ __forceinline__ u32 pack_h2(float lo, float hi) {
    u32 r;
    asm("cvt.rn.f16x2.f32 %0, %1, %2;" : "=r"(r) : "f"(hi), "f"(lo));
    return r;
}
__device__ __forceinline__ void prefetch_l1(const void* p) {
    asm volatile("prefetch.global.L1 [%0];" :: "l"(p));
}

// ---------------------------------------------------------------------------
// fp16 mma.sync GEMM (round-11 verbatim, proven): 128x128 tile, 8 warps,
// K-chunk 32 (2 ksteps of m16n8k16), double-buffered smem, reg staging.
// ---------------------------------------------------------------------------
#define G_SA_LD 20
#define G_SB_LD 136
#define G_STAGE_A (128*G_SA_LD)              // 2560 words
#define G_STAGE (G_STAGE_A + 16*G_SB_LD)     // 4736 words
#define G_SMEM (2*G_STAGE*4)                 // 37888 B

__device__ __forceinline__ void gemm_stage_store(
    u32* buf, const float4* ar, const float2* br0, const float2* br1,
    int arow, int aseg, int bkp, int bcol)
{
    #pragma unroll
    for (int p = 0; p < 4; p++) {
        *(uint2*)(buf + (arow + p * 32) * G_SA_LD + aseg * 2) =
            make_uint2(pack_h2(ar[p].x, ar[p].y), pack_h2(ar[p].z, ar[p].w));
        *(uint2*)(buf + G_STAGE_A + (bkp + p * 4) * G_SB_LD + bcol) =
            make_uint2(pack_h2(br0[p].x, br1[p].x), pack_h2(br0[p].y, br1[p].y));
    }
}

__global__ void __launch_bounds__(256) mma_gemm_kernel(
    const float* __restrict__ A_ext,
    const float* __restrict__ W0, const float* __restrict__ W1,
    const float* __restrict__ W2,
    const float* __restrict__ b0, const float* __restrict__ b1,
    const float* __restrict__ b2,
    float* __restrict__ outF, int mode)
{
    extern __shared__ u32 smg[];
    const int t = threadIdx.x;
    const int wid = t >> 5, lane = t & 31;
    const int warpM = wid & 1, warpN = wid >> 1;
    const int g = lane >> 2, tg = lane & 3;
    const int row0 = blockIdx.y * 128;

    const float* A; const float* W; const float* bias; float* C; int Nw; int col0;
    if (mode == 1) {
        A = A_ext;
        const int bn = blockIdx.x;
        if (bn < 16)      { W = W0; bias = b0; C = g_Q; Nw = HIDDEN; col0 = bn * 128; }
        else if (bn < 18) { W = W1; bias = b1; C = g_K; Nw = KVW;    col0 = (bn - 16) * 128; }
        else              { W = W2; bias = b2; C = g_V; Nw = KVW;    col0 = (bn - 18) * 128; }
    } else {
        A = g_C; W = W0; bias = nullptr; C = outF; Nw = HIDDEN; col0 = blockIdx.x * 128;
    }

    float c[4][4][4];
    #pragma unroll
    for (int i = 0; i < 4; i++)
        #pragma unroll
        for (int j = 0; j < 4; j++)
            #pragma unroll
            for (int r = 0; r < 4; r++) c[i][j][r] = 0.f;

    const int arow = t >> 3;
    const int aseg = t & 7;
    const int bkp  = t >> 6;
    const int bcol = (t & 63) * 2;

    const float* Ap  = A + (size_t)(row0 + arow) * HIDDEN + aseg * 4;
    const float* Bp0 = W + (size_t)(2 * bkp) * Nw + col0 + bcol;
    const float* Bp1 = Bp0 + Nw;
    const size_t aRow32 = (size_t)32 * HIDDEN;
    const size_t bRow8  = (size_t)8 * Nw;
    const int NCH = HIDDEN >> 5;

    float4 ar[4]; float2 br0[4], br1[4];
    #pragma unroll
    for (int p = 0; p < 4; p++) {
        ar[p]  = *(const float4*)(Ap + p * aRow32);
        br0[p] = *(const float2*)(Bp0 + p * bRow8);
        br1[p] = *(const float2*)(Bp1 + p * bRow8);
    }
    gemm_stage_store(smg, ar, br0, br1, arow, aseg, bkp, bcol);
    #pragma unroll
    for (int p = 0; p < 4; p++) {
        ar[p]  = *(const float4*)(Ap + 32 + p * aRow32);
        br0[p] = *(const float2*)(Bp0 + (size_t)32 * Nw + p * bRow8);
        br1[p] = *(const float2*)(Bp1 + (size_t)32 * Nw + p * bRow8);
    }

    const int bcolw = warpN * 32;

    for (int ch = 0; ch < NCH; ch++) {
        __syncthreads();

        if (ch + 1 < NCH)
            gemm_stage_store(smg + ((ch + 1) & 1) * G_STAGE, ar, br0, br1,
                             arow, aseg, bkp, bcol);

        if (ch + 2 < NCH) {
            const int ko = (ch + 2) * 32;
            #pragma unroll
            for (int p = 0; p < 4; p++) {
                ar[p]  = *(const float4*)(Ap + ko + p * aRow32);
                br0[p] = *(const float2*)(Bp0 + (size_t)ko * Nw + p * bRow8);
                br1[p] = *(const float2*)(Bp1 + (size_t)ko * Nw + p * bRow8);
            }
        }

        const u32* sA = smg + (ch & 1) * G_STAGE;
        const u32* sB = sA + G_STAGE_A;
        const u32* sAw = sA + (warpM * 64) * G_SA_LD;

        #pragma unroll
        for (int ks = 0; ks < 2; ks++) {
            const int kw = ks * 8;
            u32 af[4][4], bf[4][2];
            #pragma unroll
            for (int i = 0; i < 4; i++) {
                const u32* base = sAw + (i * 16 + g) * G_SA_LD + kw + tg;
                af[i][0] = base[0];
                af[i][1] = base[8 * G_SA_LD];
                af[i][2] = base[4];
                af[i][3] = base[8 * G_SA_LD + 4];
            }
            #pragma unroll
            for (int j = 0; j < 4; j++) {
                const u32* base = sB + (kw + tg) * G_SB_LD + bcolw + j * 8 + g;
                bf[j][0] = base[0];
                bf[j][1] = base[4 * G_SB_LD];
            }
            #pragma unroll
            for (int i = 0; i < 4; i++)
                #pragma unroll
                for (int j = 0; j < 4; j++)
                    mma_f16(c[i][j], af[i], bf[j]);
        }
    }

    #pragma unroll
    for (int i = 0; i < 4; i++) {
        const int r0e = row0 + warpM * 64 + i * 16 + g;
        #pragma unroll
        for (int j = 0; j < 4; j++) {
            const int col = col0 + warpN * 32 + j * 8 + 2 * tg;
            float bb0 = 0.f, bb1 = 0.f;
            if (bias) { bb0 = bias[col]; bb1 = bias[col + 1]; }
            *(float2*)(C + (size_t)r0e * Nw + col) =
                make_float2(c[i][j][0] + bb0, c[i][j][1] + bb1);
            *(float2*)(C + (size_t)(r0e + 8) * Nw + col) =
                make_float2(c[i][j][2] + bb0, c[i][j][3] + bb1);
        }
    }
}

// ---------------------------------------------------------------------------
// RoPE in place (round-4 verbatim)
// ---------------------------------------------------------------------------
__global__ void rope_kernel(const float* __restrict__ cosT,
                            const float* __restrict__ sinT,
                            int nheads, int which)
{
    float* X = which ? g_Q : g_K;
    const int idx = blockIdx.x * blockDim.x + threadIdx.x;
    const int total = SEQ * nheads * 64;
    if (idx >= total) return;
    const int d = idx & 63;
    const int h = (idx >> 6) % nheads;
    const int s = idx / (64 * nheads);

    const float c1 = cosT[s * HD + d];
    const float s1 = sinT[s * HD + d];
    const float c2 = cosT[s * HD + d + 64];
    const float s2 = sinT[s * HD + d + 64];

    float* p = X + (size_t)s * (nheads * HD) + h * HD + d;
    const float x1 = p[0];
    const float x2 = p[64];
    p[0]  = x1 * c1 - x2 * s1;
    p[64] = x2 * c2 + x1 * s2;
}

// ---------------------------------------------------------------------------
// Full-fp16 flash attention (fp32 accumulate). 128 threads = 4 warps x 16 rows,
// grid 32 qtiles x 16 heads. K staged row-major half2-packed [key][d-pair]
// (LD=68, conflict-free); V transposed-pack [key-pair][d] (LD=136, R10-verified).
// L1 prefetch of next tile during current tile.
// ---------------------------------------------------------------------------
#define KLD16 68
#define VLD16 136
#define SK16_WORDS (64*KLD16)                // 4352
#define SVT_WORDS  (32*VLD16)                // 4352
#define ATTN_SMEM ((SK16_WORDS+SVT_WORDS)*4) // 34816 B

__global__ void __launch_bounds__(128) attn_mma_kernel()
{
    extern __shared__ u32 smem[];
    u32* sK16 = smem;                 // [key][dp]  64 x 68
    u32* sVT  = smem + SK16_WORDS;    // [kp][d]    32 x 136

    const int t = threadIdx.x;
    const int lane = t & 31, wid = t >> 5;
    const int g = lane >> 2, tg = lane & 3;
    const int qt = 31 - blockIdx.x;          // heavy tiles first
    const int h  = blockIdx.y;
    const int kvh = h >> 3;
    const int qbase = qt * 64 + wid * 16;
    const int r0 = qbase + g, r1 = qbase + g + 8;

    // Q fragments fp16: 8 ksteps of k=16
    u32 qf[8][4];
    const float* Qp = g_Q + (size_t)qbase * HIDDEN + h * HD;
    #pragma unroll
    for (int ks = 0; ks < 8; ks++) {
        const float2 a0 = *(const float2*)(Qp + (size_t)g * HIDDEN + ks * 16 + 2 * tg);
        const float2 a1 = *(const float2*)(Qp + (size_t)(g + 8) * HIDDEN + ks * 16 + 2 * tg);
        const float2 a2 = *(const float2*)(Qp + (size_t)g * HIDDEN + ks * 16 + 8 + 2 * tg);
        const float2 a3 = *(const float2*)(Qp + (size_t)(g + 8) * HIDDEN + ks * 16 + 8 + 2 * tg);
        qf[ks][0] = pack_h2(a0.x, a0.y);
        qf[ks][1] = pack_h2(a1.x, a1.y);
        qf[ks][2] = pack_h2(a2.x, a2.y);
        qf[ks][3] = pack_h2(a3.x, a3.y);
    }

    float o[16][4];
    #pragma unroll
    for (int n = 0; n < 16; n++)
        #pragma unroll
        for (int r = 0; r < 4; r++) o[n][r] = 0.f;
    float m0 = -1e30f, m1 = -1e30f, l0 = 0.f, l1 = 0.f;

    const int ntiles = qt + 1;

    for (int kt = 0; kt < ntiles; kt++) {
        __syncthreads();
        // ---- stage K (fp16 packed along d): 16 passes, coalesced LDG.128 ----
        #pragma unroll
        for (int p = 0; p < 16; p++) {
            const int idx = p * 128 + t;
            const int key = idx >> 5;
            const int d4 = (idx & 31) * 4;
            const float4 kk =
                *(const float4*)&g_K[(size_t)(kt * 64 + key) * KVW + kvh * HD + d4];
            *(uint2*)(sK16 + key * KLD16 + (d4 >> 1)) =
                make_uint2(pack_h2(kk.x, kk.y), pack_h2(kk.z, kk.w));
        }
        // ---- stage V transposed-pack: sVT[kp][d] = half2(V[2kp][d], V[2kp+1][d]) ----
        #pragma unroll
        for (int p = 0; p < 8; p++) {
            const int idx = p * 128 + t;
            const int kp = idx >> 5;
            const int d4 = (idx & 31) * 4;
            const size_t base = (size_t)(kt * 64 + 2 * kp) * KVW + kvh * HD + d4;
            const float4 v0 = *(const float4*)&g_V[base];
            const float4 v1 = *(const float4*)&g_V[base + KVW];
            *(uint4*)(sVT + kp * VLD16 + d4) = make_uint4(
                pack_h2(v0.x, v1.x), pack_h2(v0.y, v1.y),
                pack_h2(v0.z, v1.z), pack_h2(v0.w, v1.w));
        }
        // ---- L1 prefetch of next tile (issue-only, no stall) ----
        if (kt + 1 < ntiles) {
            #pragma unroll
            for (int q2 = 0; q2 < 2; q2++) {
                const int li = t * 2 + q2;           // 0..255
                const int row = li >> 2, seg = li & 3;
                const char* ka = (const char*)
                    &g_K[(size_t)((kt + 1) * 64 + row) * KVW + kvh * HD] + seg * 128;
                const char* va = (const char*)
                    &g_V[(size_t)((kt + 1) * 64 + row) * KVW + kvh * HD] + seg * 128;
                prefetch_l1(ka);
                prefetch_l1(va);
            }
        }
        __syncthreads();

        if (kt * 64 > qbase + 15) continue;   // fully masked for this warp

        // ---- S = Q K^T (16 x 64), fp16 k=16, 8 ksteps ----
        float c[8][4];
        #pragma unroll
        for (int j = 0; j < 8; j++)
            #pragma unroll
            for (int r = 0; r < 4; r++) c[j][r] = 0.f;

        #pragma unroll
        for (int ks = 0; ks < 8; ks++) {
            #pragma unroll
            for (int j = 0; j < 8; j++) {
                u32 bf[2];
                const u32* bb = sK16 + (j * 8 + g) * KLD16 + ks * 8 + tg;
                bf[0] = bb[0];
                bf[1] = bb[4];
                mma_f16(c[j], qf[ks], bf);
            }
        }

        // ---- scale + causal mask (C layout unchanged) ----
        const bool diag = (kt * 64 + 63 > qbase);
        #pragma unroll
        for (int j = 0; j < 8; j++) {
            const int key = kt * 64 + j * 8 + 2 * tg;
            c[j][0] *= ATT_SCALE; c[j][1] *= ATT_SCALE;
            c[j][2] *= ATT_SCALE; c[j][3] *= ATT_SCALE;
            if (diag) {
                if (key     > r0) c[j][0] = -1e30f;
                if (key + 1 > r0) c[j][1] = -1e30f;
                if (key     > r1) c[j][2] = -1e30f;
                if (key + 1 > r1) c[j][3] = -1e30f;
            }
        }

        // ---- online softmax ----
        float mx0 = m0, mx1 = m1;
        #pragma unroll
        for (int j = 0; j < 8; j++) {
            mx0 = fmaxf(mx0, fmaxf(c[j][0], c[j][1]));
            mx1 = fmaxf(mx1, fmaxf(c[j][2], c[j][3]));
        }
        mx0 = fmaxf(mx0, __shfl_xor_sync(0xffffffffu, mx0, 1));
        mx0 = fmaxf(mx0, __shfl_xor_sync(0xffffffffu, mx0, 2));
        mx1 = fmaxf(mx1, __shfl_xor_sync(0xffffffffu, mx1, 1));
        mx1 = fmaxf(mx1, __shfl_xor_sync(0xffffffffu, mx1, 2));
        const float corr0 = __expf(m0 - mx0);
        const float corr1 = __expf(m1 - mx1);
        m0 = mx0; m1 = mx1;
        l0 *= corr0; l1 *= corr1;
        #pragma unroll
        for (int n = 0; n < 16; n++) {
            o[n][0] *= corr0; o[n][1] *= corr0;
            o[n][2] *= corr1; o[n][3] *= corr1;
        }

        // ---- P = exp(S - m) packed fp16 in-register; O += P V (no shuffles) ----
        float s0 = 0.f, s1 = 0.f;
        #pragma unroll
        for (int kg = 0; kg < 4; kg++) {
            const int j0 = kg * 2, j1 = kg * 2 + 1;
            const float e00a = __expf(c[j0][0] - m0);
            const float e01a = __expf(c[j0][1] - m0);
            const float e10a = __expf(c[j0][2] - m1);
            const float e11a = __expf(c[j0][3] - m1);
            const float e00b = __expf(c[j1][0] - m0);
            const float e01b = __expf(c[j1][1] - m0);
            const float e10b = __expf(c[j1][2] - m1);
            const float e11b = __expf(c[j1][3] - m1);
            s0 += e00a + e01a + e00b + e01b;
            s1 += e10a + e11a + e10b + e11b;

            u32 af[4];
            af[0] = pack_h2(e00a, e01a);   // row g,   keys kg*16+2tg, +1
            af[1] = pack_h2(e10a, e11a);   // row g+8
            af[2] = pack_h2(e00b, e01b);   // row g,   keys kg*16+8+2tg, +1
            af[3] = pack_h2(e10b, e11b);   // row g+8

            #pragma unroll
            for (int n = 0; n < 16; n++) {
                u32 bf[2];
                const u32* bb = sVT + (kg * 8 + tg) * VLD16 + n * 8 + g;
                bf[0] = bb[0];
                bf[1] = bb[4 * VLD16];
                mma_f16(o[n], af, bf);
            }
        }
        s0 += __shfl_xor_sync(0xffffffffu, s0, 1);
        s0 += __shfl_xor_sync(0xffffffffu, s0, 2);
        s1 += __shfl_xor_sync(0xffffffffu, s1, 1);
        s1 += __shfl_xor_sync(0xffffffffu, s1, 2);
        l0 += s0; l1 += s1;
    }

    // ---- epilogue ----
    const float inv0 = 1.f / l0;
    const float inv1 = 1.f / l1;
    float* cp0 = g_C + (size_t)r0 * HIDDEN + h * HD;
    float* cp1 = g_C + (size_t)r1 * HIDDEN + h * HD;
    #pragma unroll
    for (int n = 0; n < 16; n++) {
        const int col = n * 8 + 2 * tg;
        *(float2*)(cp0 + col) = make_float2(o[n][0] * inv0, o[n][1] * inv0);
        *(float2*)(cp1 + col) = make_float2(o[n][2] * inv1, o[n][3] * inv1);
    }
}

// ---------------------------------------------------------------------------
extern "C" void kernel_launch(void* const* d_in, const int* in_sizes, int n_in,
                              void* d_out, int out_size)
{
    const float* hs   = (const float*)d_in[0];
    const float* cosT = (const float*)d_in[1];
    const float* sinT = (const float*)d_in[2];
    // d_in[3] = attention_mask (pure causal; applied analytically)
    const float* Wq = (const float*)d_in[4];
    const float* bq = (const float*)d_in[5];
    const float* Wk = (const float*)d_in[6];
    const float* bk = (const float*)d_in[7];
    const float* Wv = (const float*)d_in[8];
    const float* bv = (const float*)d_in[9];
    const float* Wo = (const float*)d_in[10];
    float* out = (float*)d_out;

    cudaFuncSetAttribute(mma_gemm_kernel,
                         cudaFuncAttributeMaxDynamicSharedMemorySize, G_SMEM);
    cudaFuncSetAttribute(attn_mma_kernel,
                         cudaFuncAttributeMaxDynamicSharedMemorySize, ATTN_SMEM);

    // fused QKV projection: blocks 0-15 -> Q, 16-17 -> K, 18-19 -> V
    mma_gemm_kernel<<<dim3(20, 16), 256, G_SMEM>>>(
        hs, Wq, Wk, Wv, bq, bk, bv, nullptr, 1);

    rope_kernel<<<(SEQ * NH  * 64 + 255) / 256, 256>>>(cosT, sinT, NH, 1);
    rope_kernel<<<(SEQ * NKV * 64 + 255) / 256, 256>>>(cosT, sinT, NKV, 0);

    attn_mma_kernel<<<dim3(32, 16), 128, ATTN_SMEM>>>();

    // O projection
    mma_gemm_kernel<<<dim3(16, 16), 256, G_SMEM>>>(
        g_C, Wo, nullptr, nullptr, nullptr, nullptr, nullptr, out, 0);
}

// round 14
// speedup vs baseline: 2.3443x; 1.0265x over previous
#include <cuda_runtime.h>

typedef unsigned int u32;

#define SEQ 2048
#define HIDDEN 2048
#define NH 16
#define NKV 2
#define HD 128
#define KVW (NKV*HD)          // 256
#define ATT_SCALE 0.08838834764831845f

// ---------------- scratch (no allocations allowed) ----------------
__device__ float g_Q[SEQ*HIDDEN];
__device__ float g_K[SEQ*KVW];
__device__ float g_V[SEQ*KVW];
__device__ float g_C[SEQ*HIDDEN];

// ---------------- helpers ----------------
__device__ __forceinline__ u32 f2tf32(float f) {
    u32 r;
    asm("cvt.rna.tf32.f32 %0, %1;" : "=r"(r) : "f"(f));
    return r;
}
__device__ __forceinline__ void mma_f16(float* c, const u32* a, const u32* b) {
    asm volatile(
        "mma.sync.aligned.m16n8k16.row.col.f32.f16.f16.f32 "
        "{%0,%1,%2,%3}, {%4,%5,%6,%7}, {%8,%9}, {%0,%1,%2,%3};"
        : "+f"(c[0]), "+f"(c[1]), "+f"(c[2]), "+f"(c[3])
        : "r"(a[0]), "r"(a[1]), "r"(a[2]), "r"(a[3]),
          "r"(b[0]), "r"(b[1]));
}
// pack two fp32 -> f16x2, 'lo' in low half (convention verified R10-R13)
__device__ __forceinline__ u32 pack_h2(float lo, float hi) {
    u32 r;
    asm("cvt.rn.f16x2.f32 %0, %1, %2;" : "=r"(r) : "f"(hi), "f"(lo));
    return r;
}
__device__ __forceinline__ void prefetch_l1(const void* p) {
    asm volatile("prefetch.global.L1 [%0];" :: "l"(p));
}

// ---------------------------------------------------------------------------
// fp16 mma.sync GEMM (round-11 verbatim, proven): 128x128 tile, 8 warps,
// K-chunk 32 (2 ksteps of m16n8k16), double-buffered smem, reg staging.
// ---------------------------------------------------------------------------
#define G_SA_LD 20
#define G_SB_LD 136
#define G_STAGE_A (128*G_SA_LD)              // 2560 words
#define G_STAGE (G_STAGE_A + 16*G_SB_LD)     // 4736 words
#define G_SMEM (2*G_STAGE*4)                 // 37888 B

__device__ __forceinline__ void gemm_stage_store(
    u32* buf, const float4* ar, const float2* br0, const float2* br1,
    int arow, int aseg, int bkp, int bcol)
{
    #pragma unroll
    for (int p = 0; p < 4; p++) {
        *(uint2*)(buf + (arow + p * 32) * G_SA_LD + aseg * 2) =
            make_uint2(pack_h2(ar[p].x, ar[p].y), pack_h2(ar[p].z, ar[p].w));
        *(uint2*)(buf + G_STAGE_A + (bkp + p * 4) * G_SB_LD + bcol) =
            make_uint2(pack_h2(br0[p].x, br1[p].x), pack_h2(br0[p].y, br1[p].y));
    }
}

__global__ void __launch_bounds__(256) mma_gemm_kernel(
    const float* __restrict__ A_ext,
    const float* __restrict__ W0, const float* __restrict__ W1,
    const float* __restrict__ W2,
    const float* __restrict__ b0, const float* __restrict__ b1,
    const float* __restrict__ b2,
    float* __restrict__ outF, int mode)
{
    extern __shared__ u32 smg[];
    const int t = threadIdx.x;
    const int wid = t >> 5, lane = t & 31;
    const int warpM = wid & 1, warpN = wid >> 1;
    const int g = lane >> 2, tg = lane & 3;
    const int row0 = blockIdx.y * 128;

    const float* A; const float* W; const float* bias; float* C; int Nw; int col0;
    if (mode == 1) {
        A = A_ext;
        const int bn = blockIdx.x;
        if (bn < 16)      { W = W0; bias = b0; C = g_Q; Nw = HIDDEN; col0 = bn * 128; }
        else if (bn < 18) { W = W1; bias = b1; C = g_K; Nw = KVW;    col0 = (bn - 16) * 128; }
        else              { W = W2; bias = b2; C = g_V; Nw = KVW;    col0 = (bn - 18) * 128; }
    } else {
        A = g_C; W = W0; bias = nullptr; C = outF; Nw = HIDDEN; col0 = blockIdx.x * 128;
    }

    float c[4][4][4];
    #pragma unroll
    for (int i = 0; i < 4; i++)
        #pragma unroll
        for (int j = 0; j < 4; j++)
            #pragma unroll
            for (int r = 0; r < 4; r++) c[i][j][r] = 0.f;

    const int arow = t >> 3;
    const int aseg = t & 7;
    const int bkp  = t >> 6;
    const int bcol = (t & 63) * 2;

    const float* Ap  = A + (size_t)(row0 + arow) * HIDDEN + aseg * 4;
    const float* Bp0 = W + (size_t)(2 * bkp) * Nw + col0 + bcol;
    const float* Bp1 = Bp0 + Nw;
    const size_t aRow32 = (size_t)32 * HIDDEN;
    const size_t bRow8  = (size_t)8 * Nw;
    const int NCH = HIDDEN >> 5;

    float4 ar[4]; float2 br0[4], br1[4];
    #pragma unroll
    for (int p = 0; p < 4; p++) {
        ar[p]  = *(const float4*)(Ap + p * aRow32);
        br0[p] = *(const float2*)(Bp0 + p * bRow8);
        br1[p] = *(const float2*)(Bp1 + p * bRow8);
    }
    gemm_stage_store(smg, ar, br0, br1, arow, aseg, bkp, bcol);
    #pragma unroll
    for (int p = 0; p < 4; p++) {
        ar[p]  = *(const float4*)(Ap + 32 + p * aRow32);
        br0[p] = *(const float2*)(Bp0 + (size_t)32 * Nw + p * bRow8);
        br1[p] = *(const float2*)(Bp1 + (size_t)32 * Nw + p * bRow8);
    }

    const int bcolw = warpN * 32;

    for (int ch = 0; ch < NCH; ch++) {
        __syncthreads();

        if (ch + 1 < NCH)
            gemm_stage_store(smg + ((ch + 1) & 1) * G_STAGE, ar, br0, br1,
                             arow, aseg, bkp, bcol);

        if (ch + 2 < NCH) {
            const int ko = (ch + 2) * 32;
            #pragma unroll
            for (int p = 0; p < 4; p++) {
                ar[p]  = *(const float4*)(Ap + ko + p * aRow32);
                br0[p] = *(const float2*)(Bp0 + (size_t)ko * Nw + p * bRow8);
                br1[p] = *(const float2*)(Bp1 + (size_t)ko * Nw + p * bRow8);
            }
        }

        const u32* sA = smg + (ch & 1) * G_STAGE;
        const u32* sB = sA + G_STAGE_A;
        const u32* sAw = sA + (warpM * 64) * G_SA_LD;

        #pragma unroll
        for (int ks = 0; ks < 2; ks++) {
            const int kw = ks * 8;
            u32 af[4][4], bf[4][2];
            #pragma unroll
            for (int i = 0; i < 4; i++) {
                const u32* base = sAw + (i * 16 + g) * G_SA_LD + kw + tg;
                af[i][0] = base[0];
                af[i][1] = base[8 * G_SA_LD];
                af[i][2] = base[4];
                af[i][3] = base[8 * G_SA_LD + 4];
            }
            #pragma unroll
            for (int j = 0; j < 4; j++) {
                const u32* base = sB + (kw + tg) * G_SB_LD + bcolw + j * 8 + g;
                bf[j][0] = base[0];
                bf[j][1] = base[4 * G_SB_LD];
            }
            #pragma unroll
            for (int i = 0; i < 4; i++)
                #pragma unroll
                for (int j = 0; j < 4; j++)
                    mma_f16(c[i][j], af[i], bf[j]);
        }
    }

    #pragma unroll
    for (int i = 0; i < 4; i++) {
        const int r0e = row0 + warpM * 64 + i * 16 + g;
        #pragma unroll
        for (int j = 0; j < 4; j++) {
            const int col = col0 + warpN * 32 + j * 8 + 2 * tg;
            float bb0 = 0.f, bb1 = 0.f;
            if (bias) { bb0 = bias[col]; bb1 = bias[col + 1]; }
            *(float2*)(C + (size_t)r0e * Nw + col) =
                make_float2(c[i][j][0] + bb0, c[i][j][1] + bb1);
            *(float2*)(C + (size_t)(r0e + 8) * Nw + col) =
                make_float2(c[i][j][2] + bb0, c[i][j][3] + bb1);
        }
    }
}

// ---------------------------------------------------------------------------
// RoPE in place (round-4 verbatim)
// ---------------------------------------------------------------------------
__global__ void rope_kernel(const float* __restrict__ cosT,
                            const float* __restrict__ sinT,
                            int nheads, int which)
{
    float* X = which ? g_Q : g_K;
    const int idx = blockIdx.x * blockDim.x + threadIdx.x;
    const int total = SEQ * nheads * 64;
    if (idx >= total) return;
    const int d = idx & 63;
    const int h = (idx >> 6) % nheads;
    const int s = idx / (64 * nheads);

    const float c1 = cosT[s * HD + d];
    const float s1 = sinT[s * HD + d];
    const float c2 = cosT[s * HD + d + 64];
    const float s2 = sinT[s * HD + d + 64];

    float* p = X + (size_t)s * (nheads * HD) + h * HD + d;
    const float x1 = p[0];
    const float x2 = p[64];
    p[0]  = x1 * c1 - x2 * s1;
    p[64] = x2 * c2 + x1 * s2;
}

// ---------------------------------------------------------------------------
// Full-fp16 flash attention with DOUBLE-BUFFERED single-barrier staging.
// 128 threads = 4 warps x 16 rows, grid 32 qtiles x 16 heads.
// Loop: compute(buf[kt&1]) -> stage(kt+1 -> buf[~kt&1]) -> ONE barrier.
// K staged [key][d-pair] (LD=68), V transposed-pack [key-pair][d] (LD=136).
// ---------------------------------------------------------------------------
#define KLD16 68
#define VLD16 136
#define SK16_WORDS (64*KLD16)                // 4352
#define SVT_WORDS  (32*VLD16)                // 4352
#define A_STG (SK16_WORDS + SVT_WORDS)       // 8704 words per stage
#define ATTN_SMEM (2*A_STG*4)                // 69632 B

__device__ __forceinline__ void attn_stage(
    u32* buf, int kt, int ntiles, int kvh, int t)
{
    u32* bK = buf;
    u32* bV = buf + SK16_WORDS;
    // K: 16 passes, coalesced LDG.128, packed along d
    #pragma unroll
    for (int p = 0; p < 16; p++) {
        const int idx = p * 128 + t;
        const int key = idx >> 5;
        const int d4 = (idx & 31) * 4;
        const float4 kk =
            *(const float4*)&g_K[(size_t)(kt * 64 + key) * KVW + kvh * HD + d4];
        *(uint2*)(bK + key * KLD16 + (d4 >> 1)) =
            make_uint2(pack_h2(kk.x, kk.y), pack_h2(kk.z, kk.w));
    }
    // V transposed-pack: bV[kp][d] = half2(V[2kp][d], V[2kp+1][d])
    #pragma unroll
    for (int p = 0; p < 8; p++) {
        const int idx = p * 128 + t;
        const int kp = idx >> 5;
        const int d4 = (idx & 31) * 4;
        const size_t base = (size_t)(kt * 64 + 2 * kp) * KVW + kvh * HD + d4;
        const float4 v0 = *(const float4*)&g_V[base];
        const float4 v1 = *(const float4*)&g_V[base + KVW];
        *(uint4*)(bV + kp * VLD16 + d4) = make_uint4(
            pack_h2(v0.x, v1.x), pack_h2(v0.y, v1.y),
            pack_h2(v0.z, v1.z), pack_h2(v0.w, v1.w));
    }
    // L1 prefetch one tile further ahead
    if (kt + 1 < ntiles) {
        #pragma unroll
        for (int q2 = 0; q2 < 2; q2++) {
            const int li = t * 2 + q2;           // 0..255
            const int row = li >> 2, seg = li & 3;
            const char* ka = (const char*)
                &g_K[(size_t)((kt + 1) * 64 + row) * KVW + kvh * HD] + seg * 128;
            const char* va = (const char*)
                &g_V[(size_t)((kt + 1) * 64 + row) * KVW + kvh * HD] + seg * 128;
            prefetch_l1(ka);
            prefetch_l1(va);
        }
    }
}

__global__ void __launch_bounds__(128) attn_mma_kernel()
{
    extern __shared__ u32 smem[];

    const int t = threadIdx.x;
    const int lane = t & 31, wid = t >> 5;
    const int g = lane >> 2, tg = lane & 3;
    const int qt = 31 - blockIdx.x;          // heavy tiles first
    const int h  = blockIdx.y;
    const int kvh = h >> 3;
    const int qbase = qt * 64 + wid * 16;
    const int r0 = qbase + g, r1 = qbase + g + 8;

    // Q fragments fp16: 8 ksteps of k=16
    u32 qf[8][4];
    const float* Qp = g_Q + (size_t)qbase * HIDDEN + h * HD;
    #pragma unroll
    for (int ks = 0; ks < 8; ks++) {
        const float2 a0 = *(const float2*)(Qp + (size_t)g * HIDDEN + ks * 16 + 2 * tg);
        const float2 a1 = *(const float2*)(Qp + (size_t)(g + 8) * HIDDEN + ks * 16 + 2 * tg);
        const float2 a2 = *(const float2*)(Qp + (size_t)g * HIDDEN + ks * 16 + 8 + 2 * tg);
        const float2 a3 = *(const float2*)(Qp + (size_t)(g + 8) * HIDDEN + ks * 16 + 8 + 2 * tg);
        qf[ks][0] = pack_h2(a0.x, a0.y);
        qf[ks][1] = pack_h2(a1.x, a1.y);
        qf[ks][2] = pack_h2(a2.x, a2.y);
        qf[ks][3] = pack_h2(a3.x, a3.y);
    }

    float o[16][4];
    #pragma unroll
    for (int n = 0; n < 16; n++)
        #pragma unroll
        for (int r = 0; r < 4; r++) o[n][r] = 0.f;
    float m0 = -1e30f, m1 = -1e30f, l0 = 0.f, l1 = 0.f;

    const int ntiles = qt + 1;

    // prologue: stage tile 0 into buf0
    attn_stage(smem, 0, ntiles, kvh, t);
    __syncthreads();

    for (int kt = 0; kt < ntiles; kt++) {
        const u32* sK16 = smem + (kt & 1) * A_STG;
        const u32* sVT  = sK16 + SK16_WORDS;

        if (kt * 64 <= qbase + 15) {   // not fully masked for this warp
            // ---- S = Q K^T (16 x 64), fp16 k=16, 8 ksteps ----
            float c[8][4];
            #pragma unroll
            for (int j = 0; j < 8; j++)
                #pragma unroll
                for (int r = 0; r < 4; r++) c[j][r] = 0.f;

            #pragma unroll
            for (int ks = 0; ks < 8; ks++) {
                #pragma unroll
                for (int j = 0; j < 8; j++) {
                    u32 bf[2];
                    const u32* bb = sK16 + (j * 8 + g) * KLD16 + ks * 8 + tg;
                    bf[0] = bb[0];
                    bf[1] = bb[4];
                    mma_f16(c[j], qf[ks], bf);
                }
            }

            // ---- scale + causal mask ----
            const bool diag = (kt * 64 + 63 > qbase);
            #pragma unroll
            for (int j = 0; j < 8; j++) {
                const int key = kt * 64 + j * 8 + 2 * tg;
                c[j][0] *= ATT_SCALE; c[j][1] *= ATT_SCALE;
                c[j][2] *= ATT_SCALE; c[j][3] *= ATT_SCALE;
                if (diag) {
                    if (key     > r0) c[j][0] = -1e30f;
                    if (key + 1 > r0) c[j][1] = -1e30f;
                    if (key     > r1) c[j][2] = -1e30f;
                    if (key + 1 > r1) c[j][3] = -1e30f;
                }
            }

            // ---- online softmax ----
            float mx0 = m0, mx1 = m1;
            #pragma unroll
            for (int j = 0; j < 8; j++) {
                mx0 = fmaxf(mx0, fmaxf(c[j][0], c[j][1]));
                mx1 = fmaxf(mx1, fmaxf(c[j][2], c[j][3]));
            }
            mx0 = fmaxf(mx0, __shfl_xor_sync(0xffffffffu, mx0, 1));
            mx0 = fmaxf(mx0, __shfl_xor_sync(0xffffffffu, mx0, 2));
            mx1 = fmaxf(mx1, __shfl_xor_sync(0xffffffffu, mx1, 1));
            mx1 = fmaxf(mx1, __shfl_xor_sync(0xffffffffu, mx1, 2));
            const float corr0 = __expf(m0 - mx0);
            const float corr1 = __expf(m1 - mx1);
            m0 = mx0; m1 = mx1;
            l0 *= corr0; l1 *= corr1;
            #pragma unroll
            for (int n = 0; n < 16; n++) {
                o[n][0] *= corr0; o[n][1] *= corr0;
                o[n][2] *= corr1; o[n][3] *= corr1;
            }

            // ---- P = exp(S - m) packed fp16 in-register; O += P V ----
            float s0 = 0.f, s1 = 0.f;
            #pragma unroll
            for (int kg = 0; kg < 4; kg++) {
                const int j0 = kg * 2, j1 = kg * 2 + 1;
                const float e00a = __expf(c[j0][0] - m0);
                const float e01a = __expf(c[j0][1] - m0);
                const float e10a = __expf(c[j0][2] - m1);
                const float e11a = __expf(c[j0][3] - m1);
                const float e00b = __expf(c[j1][0] - m0);
                const float e01b = __expf(c[j1][1] - m0);
                const float e10b = __expf(c[j1][2] - m1);
                const float e11b = __expf(c[j1][3] - m1);
                s0 += e00a + e01a + e00b + e01b;
                s1 += e10a + e11a + e10b + e11b;

                u32 af[4];
                af[0] = pack_h2(e00a, e01a);
                af[1] = pack_h2(e10a, e11a);
                af[2] = pack_h2(e00b, e01b);
                af[3] = pack_h2(e10b, e11b);

                #pragma unroll
                for (int n = 0; n < 16; n++) {
                    u32 bf[2];
                    const u32* bb = sVT + (kg * 8 + tg) * VLD16 + n * 8 + g;
                    bf[0] = bb[0];
                    bf[1] = bb[4 * VLD16];
                    mma_f16(o[n], af, bf);
                }
            }
            s0 += __shfl_xor_sync(0xffffffffu, s0, 1);
            s0 += __shfl_xor_sync(0xffffffffu, s0, 2);
            s1 += __shfl_xor_sync(0xffffffffu, s1, 1);
            s1 += __shfl_xor_sync(0xffffffffu, s1, 2);
            l0 += s0; l1 += s1;
        }

        // stage next tile into the other buffer (overlaps other warps' compute)
        if (kt + 1 < ntiles)
            attn_stage(smem + ((kt + 1) & 1) * A_STG, kt + 1, ntiles, kvh, t);

        __syncthreads();
    }

    // ---- epilogue ----
    const float inv0 = 1.f / l0;
    const float inv1 = 1.f / l1;
    float* cp0 = g_C + (size_t)r0 * HIDDEN + h * HD;
    float* cp1 = g_C + (size_t)r1 * HIDDEN + h * HD;
    #pragma unroll
    for (int n = 0; n < 16; n++) {
        const int col = n * 8 + 2 * tg;
        *(float2*)(cp0 + col) = make_float2(o[n][0] * inv0, o[n][1] * inv0);
        *(float2*)(cp1 + col) = make_float2(o[n][2] * inv1, o[n][3] * inv1);
    }
}

// ---------------------------------------------------------------------------
extern "C" void kernel_launch(void* const* d_in, const int* in_sizes, int n_in,
                              void* d_out, int out_size)
{
    const float* hs   = (const float*)d_in[0];
    const float* cosT = (const float*)d_in[1];
    const float* sinT = (const float*)d_in[2];
    // d_in[3] = attention_mask (pure causal; applied analytically)
    const float* Wq = (const float*)d_in[4];
    const float* bq = (const float*)d_in[5];
    const float* Wk = (const float*)d_in[6];
    const float* bk = (const float*)d_in[7];
    const float* Wv = (const float*)d_in[8];
    const float* bv = (const float*)d_in[9];
    const float* Wo = (const float*)d_in[10];
    float* out = (float*)d_out;

    cudaFuncSetAttribute(mma_gemm_kernel,
                         cudaFuncAttributeMaxDynamicSharedMemorySize, G_SMEM);
    cudaFuncSetAttribute(attn_mma_kernel,
                         cudaFuncAttributeMaxDynamicSharedMemorySize, ATTN_SMEM);

    // fused QKV projection: blocks 0-15 -> Q, 16-17 -> K, 18-19 -> V
    mma_gemm_kernel<<<dim3(20, 16), 256, G_SMEM>>>(
        hs, Wq, Wk, Wv, bq, bk, bv, nullptr, 1);

    rope_kernel<<<(SEQ * NH  * 64 + 255) / 256, 256>>>(cosT, sinT, NH, 1);
    rope_kernel<<<(SEQ * NKV * 64 + 255) / 256, 256>>>(cosT, sinT, NKV, 0);

    attn_mma_kernel<<<dim3(32, 16), 128, ATTN_SMEM>>>();

    // O projection
    mma_gemm_kernel<<<dim3(16, 16), 256, G_SMEM>>>(
        g_C, Wo, nullptr, nullptr, nullptr, nullptr, nullptr, out, 0);
}